// round 6
// baseline (speedup 1.0000x reference)
#include <cuda_runtime.h>
#include <math.h>
#include <stdint.h>

#define BATCHN  16
#define SEQL    2048
#define INDIM   64
#define HID     256
#define STATEN  256
#define MLPD    1024
#define OUTD    128
#define NLAYERS 4
#define M_TOT   (BATCHN*SEQL)   /* 32768 */
#define CH      64
#define NCH     (SEQL/CH)       /* 32 */
#define LOG2CH  6
#define S2      (2*STATEN)      /* 512 */

// ---------------- scratch (static device globals) ---------------------------
__device__ float g_h  [M_TOT*HID];
__device__ float g_y  [M_TOT*HID];
__device__ float g_bu [M_TOT*S2];
__device__ float g_st [M_TOT*S2];
__device__ float g_z  [M_TOT*MLPD];
__device__ float g_xr  [M_TOT*INDIM];
__device__ float g_wE  [HID*INDIM];
__device__ float g_wB  [NLAYERS*S2*HID];     // [l][512][256] : Bre stacked on Bim
__device__ float g_wC  [NLAYERS*HID*S2];     // [l][256][512] : [Cre | -Cim]
__device__ float g_wH  [NLAYERS*MLPD*HID];
__device__ float g_wO  [NLAYERS*HID*MLPD];
__device__ float g_wOut[OUTD*HID];

__device__ __forceinline__ float rtf(float x){
    uint32_t r; asm("cvt.rna.tf32.f32 %0, %1;" : "=r"(r) : "f"(x));
    return __uint_as_float(r);
}

// ==================== hybrid GEMM ===========================================
// C[M,N] = epi(A[M,K] @ W[N,K]^T), operands tf32-valued fp32.
// Blocks by < MBT: tensor-core (mma.sync tf32) path.
// Blocks by >= MBT: FFMA path (different pipe -> runs concurrently).
// epi: 0 raw | 1 +bias | 2 rtf(gelu(+bias)) | 3 rtf(+bias+resid)
//      6 rtf(+bias) | 7 rtf(+ bias[c]*resid)
#define BM   128
#define BN   128
#define BK   16
#define ASTR 20
#define NSTG 3
#define SMEM_BYTES (NSTG*(BM+BN)*ASTR*4)   /* 61440 */

__device__ __forceinline__ void cp16(uint32_t dst, const float* src){
    asm volatile("cp.async.ca.shared.global [%0], [%1], 16;\n" :: "r"(dst), "l"(src));
}
__device__ __forceinline__ void mma_tf32(float* c, const uint32_t* a, const uint32_t* b){
    asm volatile("mma.sync.aligned.m16n8k8.row.col.f32.tf32.tf32.f32 "
        "{%0,%1,%2,%3}, {%4,%5,%6,%7}, {%8,%9}, {%0,%1,%2,%3};"
        : "+f"(c[0]), "+f"(c[1]), "+f"(c[2]), "+f"(c[3])
        : "r"(a[0]), "r"(a[1]), "r"(a[2]), "r"(a[3]), "r"(b[0]), "r"(b[1]));
}

__device__ __forceinline__ float epi_val(int epi, float a, int c, size_t ro_j,
                                         const float* __restrict__ bias,
                                         const float* __restrict__ resid)
{
    if (epi == 0) return a;
    if (epi == 1) return a + bias[c];
    if (epi == 2) {
        float t = a + bias[c];
        return rtf(0.5f * t * (1.0f + erff(t * 0.70710678118654752f)));
    }
    if (epi == 3) return rtf(a + bias[c] + resid[ro_j]);
    if (epi == 6) return rtf(a + bias[c]);
    return rtf(a + bias[c] * resid[ro_j]);   // 7
}

__global__ __launch_bounds__(256)
void gemm_hybrid(int M, int N, int K, int MBT,
                 const float* __restrict__ A, const float* __restrict__ W,
                 const float* __restrict__ bias, const float* __restrict__ resid,
                 float* __restrict__ C, int epi)
{
    extern __shared__ __align__(16) float smem[];
    int tid  = threadIdx.x;
    int by   = blockIdx.y;
    int col0 = blockIdx.x * BN;

    if (by < MBT) {
        // ================= tensor-core path (proven R4 code, BN=128) =========
        constexpr int NT    = BN/32;           // 4
        constexpr int SLOTA = BM*ASTR;
        constexpr int SLOTB = BN*ASTR;
        float* As = smem;
        float* Bs = smem + NSTG*SLOTA;

        int lane = tid & 31;
        int wid  = tid >> 5;
        int gr   = lane >> 2;
        int ct   = lane & 3;
        int wm   = (wid >> 2) * 64;
        int wn   = (wid & 3) * (BN/4);
        int row0 = by * BM;

        int lrow = tid >> 1;
        int loff = (tid & 1) * 8;
        const float* Ag = A + (size_t)(row0 + lrow) * K + loff;
        const float* Wg = W + (size_t)(col0 + lrow) * K + loff;
        uint32_t sAb = (uint32_t)__cvta_generic_to_shared(&As[lrow*ASTR + loff]);
        uint32_t sBb = (uint32_t)__cvta_generic_to_shared(&Bs[lrow*ASTR + loff]);

        float acc[4][NT][4];
        #pragma unroll
        for (int i=0;i<4;i++)
            #pragma unroll
            for (int j=0;j<NT;j++)
                #pragma unroll
                for (int q=0;q<4;q++) acc[i][j][q] = 0.f;

        int nk = K / BK;

        auto load_stage = [&](int kt){
            int slot = kt % NSTG;
            int k0 = kt * BK;
            cp16(sAb + slot*SLOTA*4,      Ag + k0);
            cp16(sAb + slot*SLOTA*4 + 16, Ag + k0 + 4);
            cp16(sBb + slot*SLOTB*4,      Wg + k0);
            cp16(sBb + slot*SLOTB*4 + 16, Wg + k0 + 4);
            asm volatile("cp.async.commit_group;\n");
        };

        load_stage(0);
        load_stage(1);

        for (int kt = 0; kt < nk; kt++) {
            asm volatile("cp.async.wait_group 1;\n");
            __syncthreads();
            if (kt + 2 < nk) load_stage(kt + 2);
            else             asm volatile("cp.async.commit_group;\n");

            int slot = kt % NSTG;
            const uint32_t* Asm = (const uint32_t*)&As[slot*SLOTA];
            const uint32_t* Bsm = (const uint32_t*)&Bs[slot*SLOTB];
            #pragma unroll
            for (int ks = 0; ks < 2; ks++) {
                int kk = ks*8 + ct;
                uint32_t ua[4][4], ub[NT][2];
                #pragma unroll
                for (int mt = 0; mt < 4; mt++) {
                    int r = wm + mt*16 + gr;
                    ua[mt][0] = Asm[ r      *ASTR + kk    ];
                    ua[mt][1] = Asm[(r + 8)*ASTR + kk    ];
                    ua[mt][2] = Asm[ r      *ASTR + kk + 4];
                    ua[mt][3] = Asm[(r + 8)*ASTR + kk + 4];
                }
                #pragma unroll
                for (int nt = 0; nt < NT; nt++) {
                    int n = wn + nt*8 + gr;
                    ub[nt][0] = Bsm[n*ASTR + kk    ];
                    ub[nt][1] = Bsm[n*ASTR + kk + 4];
                }
                #pragma unroll
                for (int mt = 0; mt < 4; mt++)
                    #pragma unroll
                    for (int nt = 0; nt < NT; nt++)
                        mma_tf32(acc[mt][nt], ua[mt], ub[nt]);
            }
        }

        #pragma unroll
        for (int mt = 0; mt < 4; mt++) {
            #pragma unroll
            for (int half = 0; half < 2; half++) {
                int r = row0 + wm + mt*16 + gr + half*8;
                size_t ro = (size_t)r * N;
                #pragma unroll
                for (int nt = 0; nt < NT; nt++) {
                    int cc = col0 + wn + nt*8 + ct*2;
                    C[ro + cc]     = epi_val(epi, acc[mt][nt][half*2+0], cc,   ro+cc,   bias, resid);
                    C[ro + cc + 1] = epi_val(epi, acc[mt][nt][half*2+1], cc+1, ro+cc+1, bias, resid);
                }
            }
        }
    } else {
        // ================= FFMA path (fma pipe) ==============================
        constexpr int FST = 132;               // padded row stride
        float* Af = smem;                      // [16][132]
        float* Bf = smem + 16*FST;             // [16][132]

        int tx = tid & 15;                     // 0..15 -> col micro
        int ty = tid >> 4;                     // 0..15 -> row micro
        int row0 = by * BM;                    // by >= MBT rows handled here

        int lrow = tid >> 1;
        int loff = (tid & 1) * 8;
        const float* Ag = A + (size_t)(row0 + lrow) * K + loff;
        const float* Wg = W + (size_t)(col0 + lrow) * K + loff;

        float acc[8][8];
        #pragma unroll
        for (int i=0;i<8;i++)
            #pragma unroll
            for (int j=0;j<8;j++) acc[i][j] = 0.f;

        for (int k0 = 0; k0 < K; k0 += 16) {
            float4 a0 = *(const float4*)(Ag + k0);
            float4 a1 = *(const float4*)(Ag + k0 + 4);
            float4 b0 = *(const float4*)(Wg + k0);
            float4 b1 = *(const float4*)(Wg + k0 + 4);
            __syncthreads();
            Af[(loff+0)*FST + lrow] = a0.x; Af[(loff+1)*FST + lrow] = a0.y;
            Af[(loff+2)*FST + lrow] = a0.z; Af[(loff+3)*FST + lrow] = a0.w;
            Af[(loff+4)*FST + lrow] = a1.x; Af[(loff+5)*FST + lrow] = a1.y;
            Af[(loff+6)*FST + lrow] = a1.z; Af[(loff+7)*FST + lrow] = a1.w;
            Bf[(loff+0)*FST + lrow] = b0.x; Bf[(loff+1)*FST + lrow] = b0.y;
            Bf[(loff+2)*FST + lrow] = b0.z; Bf[(loff+3)*FST + lrow] = b0.w;
            Bf[(loff+4)*FST + lrow] = b1.x; Bf[(loff+5)*FST + lrow] = b1.y;
            Bf[(loff+6)*FST + lrow] = b1.z; Bf[(loff+7)*FST + lrow] = b1.w;
            __syncthreads();
            #pragma unroll
            for (int kk = 0; kk < 16; kk++) {
                float4 av0 = *(const float4*)&Af[kk*FST + ty*8];
                float4 av1 = *(const float4*)&Af[kk*FST + ty*8 + 4];
                float4 bv0 = *(const float4*)&Bf[kk*FST + tx*8];
                float4 bv1 = *(const float4*)&Bf[kk*FST + tx*8 + 4];
                float a[8] = {av0.x,av0.y,av0.z,av0.w,av1.x,av1.y,av1.z,av1.w};
                float b[8] = {bv0.x,bv0.y,bv0.z,bv0.w,bv1.x,bv1.y,bv1.z,bv1.w};
                #pragma unroll
                for (int i = 0; i < 8; i++)
                    #pragma unroll
                    for (int j = 0; j < 8; j++)
                        acc[i][j] = fmaf(a[i], b[j], acc[i][j]);
            }
        }

        #pragma unroll
        for (int i = 0; i < 8; i++) {
            int r = row0 + ty*8 + i;
            size_t ro = (size_t)r * N;
            #pragma unroll
            for (int j = 0; j < 8; j++) {
                int cc = col0 + tx*8 + j;
                C[ro + cc] = epi_val(epi, acc[i][j], cc, ro+cc, bias, resid);
            }
        }
    }
}

// ==================== weight prep (tf32 rounding / concat) ==================
__global__ void round_copy4(float4* __restrict__ dst, const float4* __restrict__ src, int n4)
{
    int i = blockIdx.x * blockDim.x + threadIdx.x;
    if (i < n4) {
        float4 v = src[i];
        v.x = rtf(v.x); v.y = rtf(v.y); v.z = rtf(v.z); v.w = rtf(v.w);
        dst[i] = v;
    }
}
__global__ void build_bcat(const float* __restrict__ Bre, const float* __restrict__ Bim)
{
    int i = blockIdx.x * blockDim.x + threadIdx.x;     // NLAYERS*512*256
    int k = i & (HID-1);
    int row = (i >> 8) & (S2-1);
    int l = i >> 17;
    float v = (row < STATEN) ? Bre[((size_t)l*STATEN + row)*HID + k]
                             : Bim[((size_t)l*STATEN + row - STATEN)*HID + k];
    g_wB[i] = rtf(v);
}
__global__ void build_ccat(const float* __restrict__ Cre, const float* __restrict__ Cim)
{
    int i = blockIdx.x * blockDim.x + threadIdx.x;     // NLAYERS*256*512
    int k = i & (S2-1);
    int hh = (i >> 9) & (HID-1);
    int l = i >> 17;
    float v = (k < STATEN) ?  Cre[((size_t)l*HID + hh)*STATEN + k]
                           : -Cim[((size_t)l*HID + hh)*STATEN + k - STATEN];
    g_wC[i] = rtf(v);
}

// ==================== fused LRU scan ========================================
__device__ __forceinline__ void lam_of(const float* nu_log, const float* th_log,
                                       int layer, int s, float& lre, float& lim)
{
    float nu = nu_log[layer*STATEN + s];
    float th = th_log[layer*STATEN + s];
    float mag = expf(-expf(nu));
    float ang = expf(th);
    float sv, cv;
    sincosf(ang, &sv, &cv);
    lre = mag * cv;
    lim = mag * sv;
}

// grid: (STATEN/32, BATCHN), block: 1024 = 32 chunks x 32 states
__global__ __launch_bounds__(1024)
void scan_fused(const float* __restrict__ nu_log, const float* __restrict__ th_log,
                const float* __restrict__ gl_log, int layer)
{
    __shared__ float se_r[NCH][32], se_i[NCH][32];
    __shared__ float ca_r[NCH][32], ca_i[NCH][32];

    int tid = threadIdx.x;
    int c   = tid >> 5;
    int sl  = tid & 31;
    int s   = blockIdx.x * 32 + sl;
    int b   = blockIdx.y;

    float lre, lim;
    lam_of(nu_log, th_log, layer, s, lre, lim);
    float ga = expf(gl_log[layer*STATEN + s]);

    size_t base = ((size_t)b * SEQL + (size_t)c * CH) * S2 + s;

    {
        float sr = 0.f, si = 0.f;
        #pragma unroll 4
        for (int t = 0; t < CH; t++) {
            size_t o = base + (size_t)t * S2;
            float br = g_bu[o]          * ga;
            float bi = g_bu[o + STATEN] * ga;
            float nr = fmaf(lre, sr, fmaf(-lim, si, br));
            float ni = fmaf(lre, si, fmaf( lim, sr, bi));
            sr = nr; si = ni;
        }
        se_r[c][sl] = sr; se_i[c][sl] = si;
    }
    __syncthreads();

    if (tid < 32) {
        float ar = lre, ai = lim;
        #pragma unroll
        for (int q = 0; q < LOG2CH; q++) {
            float nr = ar*ar - ai*ai;
            ai = 2.f * ar * ai;
            ar = nr;
        }
        float cr = 0.f, ci = 0.f;
        #pragma unroll
        for (int c2 = 0; c2 < NCH; c2++) {
            ca_r[c2][sl] = cr; ca_i[c2][sl] = ci;
            float er = se_r[c2][sl], ei = se_i[c2][sl];
            float nr = fmaf(ar, cr, fmaf(-ai, ci, er));
            float ni = fmaf(ar, ci, fmaf( ai, cr, ei));
            cr = nr; ci = ni;
        }
    }
    __syncthreads();

    {
        float sr = ca_r[c][sl], si = ca_i[c][sl];
        #pragma unroll 4
        for (int t = 0; t < CH; t++) {
            size_t o = base + (size_t)t * S2;
            float br = g_bu[o]          * ga;
            float bi = g_bu[o + STATEN] * ga;
            float nr = fmaf(lre, sr, fmaf(-lim, si, br));
            float ni = fmaf(lre, si, fmaf( lim, sr, bi));
            sr = nr; si = ni;
            g_st[o]          = rtf(sr);
            g_st[o + STATEN] = rtf(si);
        }
    }
}

// ==================== driver ================================================
extern "C" void kernel_launch(void* const* d_in, const int* in_sizes, int n_in,
                              void* d_out, int out_size)
{
    (void)in_sizes; (void)n_in; (void)out_size;
    const float* x    = (const float*)d_in[0];
    const float* embW = (const float*)d_in[1];
    const float* embb = (const float*)d_in[2];
    const float* nu   = (const float*)d_in[3];
    const float* th   = (const float*)d_in[4];
    const float* gl   = (const float*)d_in[5];
    const float* Bre  = (const float*)d_in[6];
    const float* Bim  = (const float*)d_in[7];
    const float* Cre  = (const float*)d_in[8];
    const float* Cim  = (const float*)d_in[9];
    const float* Dv   = (const float*)d_in[10];
    const float* Wh   = (const float*)d_in[11];
    const float* bh   = (const float*)d_in[12];
    const float* Wo   = (const float*)d_in[13];
    const float* bo   = (const float*)d_in[14];
    const float* outW = (const float*)d_in[15];
    const float* outb = (const float*)d_in[16];
    float* out = (float*)d_out;

    float *h, *y, *z, *xr, *wE, *wB, *wC, *wH, *wO, *wOut, *stp, *bup;
    cudaGetSymbolAddress((void**)&h,    g_h);
    cudaGetSymbolAddress((void**)&y,    g_y);
    cudaGetSymbolAddress((void**)&z,    g_z);
    cudaGetSymbolAddress((void**)&xr,   g_xr);
    cudaGetSymbolAddress((void**)&wE,   g_wE);
    cudaGetSymbolAddress((void**)&wB,   g_wB);
    cudaGetSymbolAddress((void**)&wC,   g_wC);
    cudaGetSymbolAddress((void**)&wH,   g_wH);
    cudaGetSymbolAddress((void**)&wO,   g_wO);
    cudaGetSymbolAddress((void**)&wOut, g_wOut);
    cudaGetSymbolAddress((void**)&stp,  g_st);
    cudaGetSymbolAddress((void**)&bup,  g_bu);

    cudaFuncSetAttribute(gemm_hybrid, cudaFuncAttributeMaxDynamicSharedMemorySize, SMEM_BYTES);

    dim3 tb(256);
    const int MB  = M_TOT / BM;   // 256 row-blocks
    const int MBT = 200;          // 200 tensor blocks + 56 FFMA blocks (f=0.219)

    // ---- prep: tf32-round weights & input ----
    round_copy4<<<(M_TOT*INDIM/4+255)/256, tb>>>((float4*)xr, (const float4*)x, M_TOT*INDIM/4);
    round_copy4<<<(HID*INDIM/4+255)/256, tb>>>((float4*)wE, (const float4*)embW, HID*INDIM/4);
    round_copy4<<<(OUTD*HID/4+255)/256, tb>>>((float4*)wOut, (const float4*)outW, OUTD*HID/4);
    round_copy4<<<(NLAYERS*MLPD*HID/4+255)/256, tb>>>((float4*)wH, (const float4*)Wh, NLAYERS*MLPD*HID/4);
    round_copy4<<<(NLAYERS*HID*MLPD/4+255)/256, tb>>>((float4*)wO, (const float4*)Wo, NLAYERS*HID*MLPD/4);
    build_bcat<<<(NLAYERS*S2*HID)/256, tb>>>(Bre, Bim);
    build_ccat<<<(NLAYERS*HID*S2)/256, tb>>>(Cre, Cim);

    // embedding: h = rtf(x @ embW^T + embb)
    gemm_hybrid<<<dim3(HID/BN, MB), tb, SMEM_BYTES>>>(M_TOT, HID, INDIM, MBT, xr, wE, embb, nullptr, h, 6);

    for (int l = 0; l < NLAYERS; l++) {
        // bu = h @ Bcat^T   [M, 512]
        gemm_hybrid<<<dim3(S2/BN, MB), tb, SMEM_BYTES>>>(M_TOT, S2, HID, MBT, h, wB + (size_t)l*S2*HID,
                                                         nullptr, nullptr, bup, 0);
        // fused chunked complex scan
        scan_fused<<<dim3(STATEN/32, BATCHN), 1024>>>(nu, th, gl, l);

        // y = rtf([st_re|st_im] @ [Cre|-Cim]^T + D*h)
        gemm_hybrid<<<dim3(HID/BN, MB), tb, SMEM_BYTES>>>(M_TOT, HID, S2, MBT, stp, wC + (size_t)l*HID*S2,
                                                          Dv + (size_t)l*HID, h, y, 7);
        // MLP
        gemm_hybrid<<<dim3(MLPD/BN, MB), tb, SMEM_BYTES>>>(M_TOT, MLPD, HID, MBT, y, wH + (size_t)l*MLPD*HID,
                                                           bh + (size_t)l*MLPD, nullptr, z, 2);
        gemm_hybrid<<<dim3(HID/BN, MB), tb, SMEM_BYTES>>>(M_TOT, HID, MLPD, MBT, z, wO + (size_t)l*HID*MLPD,
                                                          bo + (size_t)l*HID, y, h, 3);
    }

    // out = h @ outW^T + outb   (no rounding)
    gemm_hybrid<<<dim3(OUTD/BN, MB), tb, SMEM_BYTES>>>(M_TOT, OUTD, HID, MBT, h, wOut, outb, nullptr, out, 1);
}

// round 7
// speedup vs baseline: 2.9334x; 2.9334x over previous
#include <cuda_runtime.h>
#include <cuda_fp16.h>
#include <math.h>
#include <stdint.h>

#define BATCHN  16
#define SEQL    2048
#define INDIM   64
#define HID     256
#define STATEN  256
#define MLPD    1024
#define OUTD    128
#define NLAYERS 4
#define M_TOT   (BATCHN*SEQL)   /* 32768 */
#define CH      64
#define NCH     (SEQL/CH)       /* 32 */
#define LOG2CH  6
#define S2      (2*STATEN)      /* 512 */

// ---------------- scratch (static device globals) ---------------------------
// activations in fp16; bu (scan input) stays fp32
__device__ __half g_h [M_TOT*HID];
__device__ __half g_y [M_TOT*HID];
__device__ float  g_bu[M_TOT*S2];        // interleaved: col 2s = re_s, 2s+1 = im_s
__device__ __half g_st[M_TOT*S2];        // interleaved likewise
__device__ __half g_z [M_TOT*MLPD];
__device__ __half g_xr  [M_TOT*INDIM];
__device__ __half g_wE  [HID*INDIM];
__device__ __half g_wB  [NLAYERS*S2*HID];   // row 2s=Bre[s], 2s+1=Bim[s]
__device__ __half g_wC  [NLAYERS*HID*S2];   // col 2s=Cre[.][s], 2s+1=-Cim[.][s]
__device__ __half g_wH  [NLAYERS*MLPD*HID];
__device__ __half g_wO  [NLAYERS*HID*MLPD];
__device__ __half g_wOut[OUTD*HID];

// ==================== FP16 tensor-core GEMM =================================
// C[M,N] = epi(A[M,K] @ W[N,K]^T); A,W fp16; accumulate fp32.
// epi: 0 raw | 1 +bias | 2 gelu(+bias) | 3 +bias+resid | 7 + bias[c]*resid
#define BM   128
#define BK   32            /* k elements per stage */
#define HSTR 40            /* padded row stride in halves (80B) */
#define NSTG 3

__device__ __forceinline__ void cp16(uint32_t dst, const void* src){
    asm volatile("cp.async.ca.shared.global [%0], [%1], 16;\n" :: "r"(dst), "l"(src));
}
__device__ __forceinline__ void mma_f16(float* c, const uint32_t* a, const uint32_t* b){
    asm volatile("mma.sync.aligned.m16n8k16.row.col.f32.f16.f16.f32 "
        "{%0,%1,%2,%3}, {%4,%5,%6,%7}, {%8,%9}, {%0,%1,%2,%3};"
        : "+f"(c[0]), "+f"(c[1]), "+f"(c[2]), "+f"(c[3])
        : "r"(a[0]), "r"(a[1]), "r"(a[2]), "r"(a[3]), "r"(b[0]), "r"(b[1]));
}

template<typename CT>
__device__ __forceinline__ void store2(CT* C, size_t off, float v0, float v1);
template<> __device__ __forceinline__ void store2<__half>(__half* C, size_t off, float v0, float v1){
    *(__half2*)(C + off) = __floats2half2_rn(v0, v1);
}
template<> __device__ __forceinline__ void store2<float>(float* C, size_t off, float v0, float v1){
    C[off] = v0; C[off+1] = v1;
}
template<typename CT>
__device__ __forceinline__ float rd(const CT* p, size_t off);
template<> __device__ __forceinline__ float rd<__half>(const __half* p, size_t off){ return __half2float(p[off]); }
template<> __device__ __forceinline__ float rd<float>(const float* p, size_t off){ return p[off]; }

template<int BN, typename CT>
__global__ __launch_bounds__(256)
void gemm_h(int M, int N, int K,
            const __half* __restrict__ A, const __half* __restrict__ W,
            const float* __restrict__ bias, const CT* __restrict__ resid,
            CT* __restrict__ C, int epi)
{
    constexpr int NT    = BN/32;                 // n fragments per warp (4 or 8)
    constexpr int NLB   = BN/64;                 // B cp16 iters per thread
    constexpr int SLOTA = BM*HSTR;               // halves
    constexpr int SLOTB = BN*HSTR;

    extern __shared__ __align__(16) __half smem[];
    __half* As = smem;
    __half* Bs = smem + NSTG*SLOTA;

    int tid  = threadIdx.x;
    int lane = tid & 31;
    int wid  = tid >> 5;
    int gr   = lane >> 2;
    int ct   = lane & 3;
    int wm   = (wid >> 2) * 64;
    int wn   = (wid & 3) * (BN/4);
    int row0 = blockIdx.y * BM;
    int col0 = blockIdx.x * BN;

    uint32_t sAb = (uint32_t)__cvta_generic_to_shared(As);
    uint32_t sBb = (uint32_t)__cvta_generic_to_shared(Bs);

    float acc[4][NT][4];
    #pragma unroll
    for (int i=0;i<4;i++)
        #pragma unroll
        for (int j=0;j<NT;j++)
            #pragma unroll
            for (int q=0;q<4;q++) acc[i][j][q] = 0.f;

    int nk = K / BK;

    auto load_stage = [&](int kt){
        int slot = kt % NSTG;
        int k0 = kt * BK;
        // A: 128 rows x 64B = 512 blocks -> 2/thread
        #pragma unroll
        for (int j = 0; j < 2; j++) {
            int id = tid + j*256;
            int r = id >> 2, kb = id & 3;
            cp16(sAb + (slot*SLOTA + r*HSTR)*2 + kb*16,
                 A + (size_t)(row0 + r)*K + k0 + kb*8);
        }
        // B: BN rows x 64B -> BN/64 per thread
        #pragma unroll
        for (int j = 0; j < NLB; j++) {
            int id = tid + j*256;
            int r = id >> 2, kb = id & 3;
            cp16(sBb + (slot*SLOTB + r*HSTR)*2 + kb*16,
                 W + (size_t)(col0 + r)*K + k0 + kb*8);
        }
        asm volatile("cp.async.commit_group;\n");
    };

    load_stage(0);
    load_stage(1);

    for (int kt = 0; kt < nk; kt++) {
        asm volatile("cp.async.wait_group 1;\n");
        __syncthreads();
        if (kt + 2 < nk) load_stage(kt + 2);
        else             asm volatile("cp.async.commit_group;\n");

        int slot = kt % NSTG;
        const uint32_t* A32 = (const uint32_t*)&As[slot*SLOTA];
        const uint32_t* B32 = (const uint32_t*)&Bs[slot*SLOTB];
        #pragma unroll
        for (int ks = 0; ks < 2; ks++) {     // two k16 steps per stage
            int kb = ks*8 + ct;              // u32 offset within row
            uint32_t ua[4][4], ub[NT][2];
            #pragma unroll
            for (int mt = 0; mt < 4; mt++) {
                int r = wm + mt*16 + gr;
                ua[mt][0] = A32[ r     *(HSTR/2) + kb    ];
                ua[mt][1] = A32[(r + 8)*(HSTR/2) + kb    ];
                ua[mt][2] = A32[ r     *(HSTR/2) + kb + 4];
                ua[mt][3] = A32[(r + 8)*(HSTR/2) + kb + 4];
            }
            #pragma unroll
            for (int nt = 0; nt < NT; nt++) {
                int n = wn + nt*8 + gr;
                ub[nt][0] = B32[n*(HSTR/2) + kb    ];
                ub[nt][1] = B32[n*(HSTR/2) + kb + 4];
            }
            #pragma unroll
            for (int mt = 0; mt < 4; mt++)
                #pragma unroll
                for (int nt = 0; nt < NT; nt++)
                    mma_f16(acc[mt][nt], ua[mt], ub[nt]);
        }
    }

    #pragma unroll
    for (int mt = 0; mt < 4; mt++) {
        #pragma unroll
        for (int half = 0; half < 2; half++) {
            int r = row0 + wm + mt*16 + gr + half*8;
            size_t ro = (size_t)r * N;
            #pragma unroll
            for (int nt = 0; nt < NT; nt++) {
                int cc = col0 + wn + nt*8 + ct*2;
                float v0 = acc[mt][nt][half*2 + 0];
                float v1 = acc[mt][nt][half*2 + 1];
                if (epi == 1) {
                    v0 += bias[cc]; v1 += bias[cc+1];
                } else if (epi == 2) {
                    float t0 = v0 + bias[cc], t1 = v1 + bias[cc+1];
                    v0 = 0.5f * t0 * (1.0f + erff(t0 * 0.70710678118654752f));
                    v1 = 0.5f * t1 * (1.0f + erff(t1 * 0.70710678118654752f));
                } else if (epi == 3) {
                    v0 += bias[cc]   + rd<CT>(resid, ro+cc);
                    v1 += bias[cc+1] + rd<CT>(resid, ro+cc+1);
                } else if (epi == 7) {
                    v0 += bias[cc]   * rd<CT>(resid, ro+cc);
                    v1 += bias[cc+1] * rd<CT>(resid, ro+cc+1);
                }
                store2<CT>(C, ro + cc, v0, v1);
            }
        }
    }
}

// ==================== weight prep (fp32 -> fp16) ============================
__global__ void to_half4(__half* __restrict__ dst, const float* __restrict__ src, int n4)
{
    int i = blockIdx.x * blockDim.x + threadIdx.x;
    if (i < n4) {
        float4 v = ((const float4*)src)[i];
        __half2 a = __floats2half2_rn(v.x, v.y);
        __half2 b = __floats2half2_rn(v.z, v.w);
        ((__half2*)dst)[i*2]   = a;
        ((__half2*)dst)[i*2+1] = b;
    }
}
// wB row rr: s=rr>>1; even -> Bre[s], odd -> Bim[s]
__global__ void build_bcat(const float* __restrict__ Bre, const float* __restrict__ Bim)
{
    int i = blockIdx.x * blockDim.x + threadIdx.x;     // NLAYERS*512*256
    int k  = i & (HID-1);
    int rr = (i >> 8) & (S2-1);
    int l  = i >> 17;
    int s  = rr >> 1;
    float v = (rr & 1) ? Bim[((size_t)l*STATEN + s)*HID + k]
                       : Bre[((size_t)l*STATEN + s)*HID + k];
    g_wB[i] = __float2half_rn(v);
}
// wC col kk: s=kk>>1; even -> Cre[h][s], odd -> -Cim[h][s]
__global__ void build_ccat(const float* __restrict__ Cre, const float* __restrict__ Cim)
{
    int i = blockIdx.x * blockDim.x + threadIdx.x;     // NLAYERS*256*512
    int kk = i & (S2-1);
    int hh = (i >> 9) & (HID-1);
    int l  = i >> 17;
    int s  = kk >> 1;
    float v = (kk & 1) ? -Cim[((size_t)l*HID + hh)*STATEN + s]
                       :  Cre[((size_t)l*HID + hh)*STATEN + s];
    g_wC[i] = __float2half_rn(v);
}

// ==================== fused LRU scan ========================================
__device__ __forceinline__ void lam_of(const float* nu_log, const float* th_log,
                                       int layer, int s, float& lre, float& lim)
{
    float nu = nu_log[layer*STATEN + s];
    float th = th_log[layer*STATEN + s];
    float mag = expf(-expf(nu));
    float ang = expf(th);
    float sv, cv;
    sincosf(ang, &sv, &cv);
    lre = mag * cv;
    lim = mag * sv;
}

// grid: (STATEN/32, BATCHN), block: 1024 = 32 chunks x 32 states
__global__ __launch_bounds__(1024)
void scan_fused(const float* __restrict__ nu_log, const float* __restrict__ th_log,
                const float* __restrict__ gl_log, int layer)
{
    __shared__ float se_r[NCH][32], se_i[NCH][32];
    __shared__ float ca_r[NCH][32], ca_i[NCH][32];

    int tid = threadIdx.x;
    int c   = tid >> 5;
    int sl  = tid & 31;
    int s   = blockIdx.x * 32 + sl;
    int b   = blockIdx.y;

    float lre, lim;
    lam_of(nu_log, th_log, layer, s, lre, lim);
    float ga = expf(gl_log[layer*STATEN + s]);

    // interleaved layout: element index (in float2/half2 units) = row*256 + s
    size_t base2 = ((size_t)b * SEQL + (size_t)c * CH) * STATEN + s;
    const float2* bu2 = (const float2*)g_bu;
    __half2*      st2 = (__half2*)g_st;

    {
        float sr = 0.f, si = 0.f;
        #pragma unroll 4
        for (int t = 0; t < CH; t++) {
            float2 u = bu2[base2 + (size_t)t * STATEN];
            float br = u.x * ga, bi = u.y * ga;
            float nr = fmaf(lre, sr, fmaf(-lim, si, br));
            float ni = fmaf(lre, si, fmaf( lim, sr, bi));
            sr = nr; si = ni;
        }
        se_r[c][sl] = sr; se_i[c][sl] = si;
    }
    __syncthreads();

    if (tid < 32) {
        float ar = lre, ai = lim;
        #pragma unroll
        for (int q = 0; q < LOG2CH; q++) {
            float nr = ar*ar - ai*ai;
            ai = 2.f * ar * ai;
            ar = nr;
        }
        float cr = 0.f, ci = 0.f;
        #pragma unroll
        for (int c2 = 0; c2 < NCH; c2++) {
            ca_r[c2][sl] = cr; ca_i[c2][sl] = ci;
            float er = se_r[c2][sl], ei = se_i[c2][sl];
            float nr = fmaf(ar, cr, fmaf(-ai, ci, er));
            float ni = fmaf(ar, ci, fmaf( ai, cr, ei));
            cr = nr; ci = ni;
        }
    }
    __syncthreads();

    {
        float sr = ca_r[c][sl], si = ca_i[c][sl];
        #pragma unroll 4
        for (int t = 0; t < CH; t++) {
            float2 u = bu2[base2 + (size_t)t * STATEN];
            float br = u.x * ga, bi = u.y * ga;
            float nr = fmaf(lre, sr, fmaf(-lim, si, br));
            float ni = fmaf(lre, si, fmaf( lim, sr, bi));
            sr = nr; si = ni;
            st2[base2 + (size_t)t * STATEN] = __floats2half2_rn(sr, si);
        }
    }
}

// ==================== driver ================================================
extern "C" void kernel_launch(void* const* d_in, const int* in_sizes, int n_in,
                              void* d_out, int out_size)
{
    (void)in_sizes; (void)n_in; (void)out_size;
    const float* x    = (const float*)d_in[0];
    const float* embW = (const float*)d_in[1];
    const float* embb = (const float*)d_in[2];
    const float* nu   = (const float*)d_in[3];
    const float* th   = (const float*)d_in[4];
    const float* gl   = (const float*)d_in[5];
    const float* Bre  = (const float*)d_in[6];
    const float* Bim  = (const float*)d_in[7];
    const float* Cre  = (const float*)d_in[8];
    const float* Cim  = (const float*)d_in[9];
    const float* Dv   = (const float*)d_in[10];
    const float* Wh   = (const float*)d_in[11];
    const float* bh   = (const float*)d_in[12];
    const float* Wo   = (const float*)d_in[13];
    const float* bo   = (const float*)d_in[14];
    const float* outW = (const float*)d_in[15];
    const float* outb = (const float*)d_in[16];
    float* out = (float*)d_out;

    __half *h, *y, *z, *xr, *wE, *wB, *wC, *wH, *wO, *wOut, *stp;
    float *bup;
    cudaGetSymbolAddress((void**)&h,    g_h);
    cudaGetSymbolAddress((void**)&y,    g_y);
    cudaGetSymbolAddress((void**)&z,    g_z);
    cudaGetSymbolAddress((void**)&xr,   g_xr);
    cudaGetSymbolAddress((void**)&wE,   g_wE);
    cudaGetSymbolAddress((void**)&wB,   g_wB);
    cudaGetSymbolAddress((void**)&wC,   g_wC);
    cudaGetSymbolAddress((void**)&wH,   g_wH);
    cudaGetSymbolAddress((void**)&wO,   g_wO);
    cudaGetSymbolAddress((void**)&wOut, g_wOut);
    cudaGetSymbolAddress((void**)&stp,  g_st);
    cudaGetSymbolAddress((void**)&bup,  g_bu);

    const int SM256 = NSTG*(BM+256)*HSTR*2;   // 92160
    const int SM128 = NSTG*(BM+128)*HSTR*2;   // 61440
    cudaFuncSetAttribute((const void*)gemm_h<256,__half>, cudaFuncAttributeMaxDynamicSharedMemorySize, SM256);
    cudaFuncSetAttribute((const void*)gemm_h<256,float>,  cudaFuncAttributeMaxDynamicSharedMemorySize, SM256);
    cudaFuncSetAttribute((const void*)gemm_h<128,float>,  cudaFuncAttributeMaxDynamicSharedMemorySize, SM128);

    dim3 tb(256);
    const int MB = M_TOT / BM;   // 256

    // ---- prep: fp16 conversion of input + weights ----
    to_half4<<<(M_TOT*INDIM/4+255)/256, tb>>>(xr, x, M_TOT*INDIM/4);
    to_half4<<<(HID*INDIM/4+255)/256, tb>>>(wE, embW, HID*INDIM/4);
    to_half4<<<(OUTD*HID/4+255)/256, tb>>>(wOut, outW, OUTD*HID/4);
    to_half4<<<(NLAYERS*MLPD*HID/4+255)/256, tb>>>(wH, Wh, NLAYERS*MLPD*HID/4);
    to_half4<<<(NLAYERS*HID*MLPD/4+255)/256, tb>>>(wO, Wo, NLAYERS*HID*MLPD/4);
    build_bcat<<<(NLAYERS*S2*HID)/256, tb>>>(Bre, Bim);
    build_ccat<<<(NLAYERS*HID*S2)/256, tb>>>(Cre, Cim);

    // embedding: h = half(x @ embW^T + embb)
    gemm_h<256,__half><<<dim3(HID/256, MB), tb, SM256>>>(M_TOT, HID, INDIM, xr, wE, embb, (const __half*)nullptr, h, 1);

    for (int l = 0; l < NLAYERS; l++) {
        // bu = h @ Bcat^T   [M, 512] fp32 (scan input unrounded)
        gemm_h<256,float><<<dim3(S2/256, MB), tb, SM256>>>(M_TOT, S2, HID, h, wB + (size_t)l*S2*HID,
                                                           (const float*)nullptr, (const float*)nullptr, bup, 0);
        // fused chunked complex scan
        scan_fused<<<dim3(STATEN/32, BATCHN), 1024>>>(nu, th, gl, l);

        // y = half([st interleaved] @ wC^T + D*h)
        gemm_h<256,__half><<<dim3(HID/256, MB), tb, SM256>>>(M_TOT, HID, S2, stp, wC + (size_t)l*HID*S2,
                                                             Dv + (size_t)l*HID, h, y, 7);
        // MLP
        gemm_h<256,__half><<<dim3(MLPD/256, MB), tb, SM256>>>(M_TOT, MLPD, HID, y, wH + (size_t)l*MLPD*HID,
                                                              bh + (size_t)l*MLPD, (const __half*)nullptr, z, 2);
        gemm_h<256,__half><<<dim3(HID/256, MB), tb, SM256>>>(M_TOT, HID, MLPD, z, wO + (size_t)l*HID*MLPD,
                                                             bo + (size_t)l*HID, y, h, 3);
    }

    // out = h @ outW^T + outb   (fp32 store)
    gemm_h<128,float><<<dim3(OUTD/128, MB), tb, SM128>>>(M_TOT, OUTD, HID, h, wOut, outb, (const float*)nullptr, out, 1);
}

// round 9
// speedup vs baseline: 3.1285x; 1.0665x over previous
#include <cuda_runtime.h>
#include <cuda_fp16.h>
#include <math.h>
#include <stdint.h>

#define BATCHN  16
#define SEQL    2048
#define INDIM   64
#define HID     256
#define STATEN  256
#define MLPD    1024
#define OUTD    128
#define NLAYERS 4
#define M_TOT   (BATCHN*SEQL)   /* 32768 */
#define CH      64
#define NCH     (SEQL/CH)       /* 32 */
#define LOG2CH  6
#define S2      (2*STATEN)      /* 512 */

// ---------------- scratch (static device globals) ---------------------------
__device__ __half g_h [M_TOT*HID];
__device__ __half g_y [M_TOT*HID];
__device__ float  g_bu[M_TOT*S2];        // interleaved: col 2s = re_s, 2s+1 = im_s
__device__ __half g_st[M_TOT*S2];        // interleaved likewise
__device__ __half g_z [M_TOT*MLPD];
__device__ __half g_xr  [M_TOT*INDIM];
__device__ __half g_wE  [HID*INDIM];
__device__ __half g_wB  [NLAYERS*S2*HID];   // row 2s=Bre[s], 2s+1=Bim[s]
__device__ __half g_wC  [NLAYERS*HID*S2];   // col 2s=Cre[.][s], 2s+1=-Cim[.][s]
__device__ __half g_wH  [NLAYERS*MLPD*HID];
__device__ __half g_wO  [NLAYERS*HID*MLPD];
__device__ __half g_wOut[OUTD*HID];

// ==================== FP16 tensor-core GEMM =================================
// C[M,N] = epi(A[M,K] @ W[N,K]^T); A,W fp16; accumulate fp32.
// epi: 0 raw | 1 +bias | 2 gelu(+bias) | 3 +bias+resid | 7 + bias[c]*resid
#define BM   128
#define BK   32            /* k elements per stage */
#define HSTR 40            /* padded row stride in halves (80B) — ldmatrix conflict-free */
#define NSTG 4

__device__ __forceinline__ void cp16(uint32_t dst, const void* src){
    asm volatile("cp.async.ca.shared.global [%0], [%1], 16;\n" :: "r"(dst), "l"(src));
}
__device__ __forceinline__ void mma_f16(float* c, const uint32_t* a, const uint32_t* b){
    asm volatile("mma.sync.aligned.m16n8k16.row.col.f32.f16.f16.f32 "
        "{%0,%1,%2,%3}, {%4,%5,%6,%7}, {%8,%9}, {%0,%1,%2,%3};"
        : "+f"(c[0]), "+f"(c[1]), "+f"(c[2]), "+f"(c[3])
        : "r"(a[0]), "r"(a[1]), "r"(a[2]), "r"(a[3]), "r"(b[0]), "r"(b[1]));
}
__device__ __forceinline__ void ldm4(uint32_t& r0, uint32_t& r1, uint32_t& r2, uint32_t& r3,
                                     uint32_t addr){
    asm volatile("ldmatrix.sync.aligned.m8n8.x4.shared.b16 {%0,%1,%2,%3}, [%4];"
        : "=r"(r0), "=r"(r1), "=r"(r2), "=r"(r3) : "r"(addr));
}

template<typename CT>
__device__ __forceinline__ void store2(CT* C, size_t off, float v0, float v1);
template<> __device__ __forceinline__ void store2<__half>(__half* C, size_t off, float v0, float v1){
    *(__half2*)(C + off) = __floats2half2_rn(v0, v1);
}
template<> __device__ __forceinline__ void store2<float>(float* C, size_t off, float v0, float v1){
    C[off] = v0; C[off+1] = v1;
}
template<typename CT>
__device__ __forceinline__ float rd(const CT* p, size_t off);
template<> __device__ __forceinline__ float rd<__half>(const __half* p, size_t off){ return __half2float(p[off]); }
template<> __device__ __forceinline__ float rd<float>(const float* p, size_t off){ return p[off]; }

template<int BN, typename CT>
__global__ __launch_bounds__(256)
void gemm_h(int M, int N, int K,
            const __half* __restrict__ A, const __half* __restrict__ W,
            const float* __restrict__ bias, const CT* __restrict__ resid,
            CT* __restrict__ C, int epi)
{
    constexpr int NT    = BN/32;                 // n fragments per warp (4 or 8)
    constexpr int NP    = NT/2;                  // B ldmatrix.x4 per ks (2 or 4)
    constexpr int NLB   = BN/64;                 // B cp16 iters per thread
    constexpr int SLOTA = BM*HSTR;               // halves
    constexpr int SLOTB = BN*HSTR;

    extern __shared__ __align__(16) __half smem[];
    __half* As = smem;
    __half* Bs = smem + NSTG*SLOTA;

    int tid  = threadIdx.x;
    int lane = tid & 31;
    int wid  = tid >> 5;
    int gr   = lane >> 2;
    int ct   = lane & 3;
    int wm   = (wid >> 2) * 64;
    int wn   = (wid & 3) * (BN/4);
    int row0 = blockIdx.y * BM;
    int col0 = blockIdx.x * BN;

    uint32_t sAb = (uint32_t)__cvta_generic_to_shared(As);
    uint32_t sBb = (uint32_t)__cvta_generic_to_shared(Bs);

    // ldmatrix per-lane base addresses (within stage 0)
    // A (x4 = m16 x k16): lane j: row +8 if (j>>3)&1, col +16B if j>=16
    uint32_t aBase = sAb + (uint32_t)((wm + ((lane>>3)&1)*8 + (lane&7))*HSTR)*2
                   + (uint32_t)(lane>>4)*16;
    // B (x4 = n16 x k16): lane j: row +8 if j>=16, col +16B if (j>>3)&1
    uint32_t bBase = sBb + (uint32_t)((wn + (lane>>4)*8 + (lane&7))*HSTR)*2
                   + (uint32_t)((lane>>3)&1)*16;

    float acc[4][NT][4];
    #pragma unroll
    for (int i=0;i<4;i++)
        #pragma unroll
        for (int j=0;j<NT;j++)
            #pragma unroll
            for (int q=0;q<4;q++) acc[i][j][q] = 0.f;

    int nk = K / BK;

    // guarded stage load: only touches memory when kt < nk; ALWAYS commits a
    // group so wait_group accounting stays consistent.
    auto load_stage = [&](int kt){
        if (kt < nk) {
            int slot = kt % NSTG;
            int k0 = kt * BK;
            #pragma unroll
            for (int j = 0; j < 2; j++) {
                int id = tid + j*256;
                int r = id >> 2, kb = id & 3;
                cp16(sAb + (slot*SLOTA + r*HSTR)*2 + kb*16,
                     A + (size_t)(row0 + r)*K + k0 + kb*8);
            }
            #pragma unroll
            for (int j = 0; j < NLB; j++) {
                int id = tid + j*256;
                int r = id >> 2, kb = id & 3;
                cp16(sBb + (slot*SLOTB + r*HSTR)*2 + kb*16,
                     W + (size_t)(col0 + r)*K + k0 + kb*8);
            }
        }
        asm volatile("cp.async.commit_group;\n");
    };

    load_stage(0);
    load_stage(1);
    load_stage(2);

    for (int kt = 0; kt < nk; kt++) {
        asm volatile("cp.async.wait_group 2;\n");
        __syncthreads();
        load_stage(kt + 3);

        int slot = kt % NSTG;
        uint32_t aSlot = aBase + slot*SLOTA*2;
        uint32_t bSlot = bBase + slot*SLOTB*2;
        #pragma unroll
        for (int ks = 0; ks < 2; ks++) {     // two k16 steps per stage
            uint32_t ua[4][4], ub[NT][2];
            #pragma unroll
            for (int mt = 0; mt < 4; mt++)
                ldm4(ua[mt][0], ua[mt][1], ua[mt][2], ua[mt][3],
                     aSlot + mt*16*HSTR*2 + ks*32);
            #pragma unroll
            for (int p = 0; p < NP; p++)
                ldm4(ub[2*p][0], ub[2*p][1], ub[2*p+1][0], ub[2*p+1][1],
                     bSlot + p*16*HSTR*2 + ks*32);
            #pragma unroll
            for (int mt = 0; mt < 4; mt++)
                #pragma unroll
                for (int nt = 0; nt < NT; nt++)
                    mma_f16(acc[mt][nt], ua[mt], ub[nt]);
        }
    }

    #pragma unroll
    for (int mt = 0; mt < 4; mt++) {
        #pragma unroll
        for (int half = 0; half < 2; half++) {
            int r = row0 + wm + mt*16 + gr + half*8;
            size_t ro = (size_t)r * N;
            #pragma unroll
            for (int nt = 0; nt < NT; nt++) {
                int cc = col0 + wn + nt*8 + ct*2;
                float v0 = acc[mt][nt][half*2 + 0];
                float v1 = acc[mt][nt][half*2 + 1];
                if (epi == 1) {
                    v0 += bias[cc]; v1 += bias[cc+1];
                } else if (epi == 2) {
                    float t0 = v0 + bias[cc], t1 = v1 + bias[cc+1];
                    v0 = 0.5f * t0 * (1.0f + erff(t0 * 0.70710678118654752f));
                    v1 = 0.5f * t1 * (1.0f + erff(t1 * 0.70710678118654752f));
                } else if (epi == 3) {
                    v0 += bias[cc]   + rd<CT>(resid, ro+cc);
                    v1 += bias[cc+1] + rd<CT>(resid, ro+cc+1);
                } else if (epi == 7) {
                    v0 += bias[cc]   * rd<CT>(resid, ro+cc);
                    v1 += bias[cc+1] * rd<CT>(resid, ro+cc+1);
                }
                store2<CT>(C, ro + cc, v0, v1);
            }
        }
    }
}

// ==================== weight prep (fp32 -> fp16) ============================
__global__ void to_half4(__half* __restrict__ dst, const float* __restrict__ src, int n4)
{
    int i = blockIdx.x * blockDim.x + threadIdx.x;
    if (i < n4) {
        float4 v = ((const float4*)src)[i];
        ((__half2*)dst)[i*2]   = __floats2half2_rn(v.x, v.y);
        ((__half2*)dst)[i*2+1] = __floats2half2_rn(v.z, v.w);
    }
}
__global__ void build_bcat(const float* __restrict__ Bre, const float* __restrict__ Bim)
{
    int i = blockIdx.x * blockDim.x + threadIdx.x;     // NLAYERS*512*256
    int k  = i & (HID-1);
    int rr = (i >> 8) & (S2-1);
    int l  = i >> 17;
    int s  = rr >> 1;
    float v = (rr & 1) ? Bim[((size_t)l*STATEN + s)*HID + k]
                       : Bre[((size_t)l*STATEN + s)*HID + k];
    g_wB[i] = __float2half_rn(v);
}
__global__ void build_ccat(const float* __restrict__ Cre, const float* __restrict__ Cim)
{
    int i = blockIdx.x * blockDim.x + threadIdx.x;     // NLAYERS*256*512
    int kk = i & (S2-1);
    int hh = (i >> 9) & (HID-1);
    int l  = i >> 17;
    int s  = kk >> 1;
    float v = (kk & 1) ? -Cim[((size_t)l*HID + hh)*STATEN + s]
                       :  Cre[((size_t)l*HID + hh)*STATEN + s];
    g_wC[i] = __float2half_rn(v);
}

// ==================== fused LRU scan ========================================
__device__ __forceinline__ void lam_of(const float* nu_log, const float* th_log,
                                       int layer, int s, float& lre, float& lim)
{
    float nu = nu_log[layer*STATEN + s];
    float th = th_log[layer*STATEN + s];
    float mag = expf(-expf(nu));
    float ang = expf(th);
    float sv, cv;
    sincosf(ang, &sv, &cv);
    lre = mag * cv;
    lim = mag * sv;
}

// grid: (STATEN/32, BATCHN), block: 1024 = 32 chunks x 32 states
__global__ __launch_bounds__(1024)
void scan_fused(const float* __restrict__ nu_log, const float* __restrict__ th_log,
                const float* __restrict__ gl_log, int layer)
{
    __shared__ float se_r[NCH][32], se_i[NCH][32];
    __shared__ float ca_r[NCH][32], ca_i[NCH][32];

    int tid = threadIdx.x;
    int c   = tid >> 5;
    int sl  = tid & 31;
    int s   = blockIdx.x * 32 + sl;
    int b   = blockIdx.y;

    float lre, lim;
    lam_of(nu_log, th_log, layer, s, lre, lim);
    float ga = expf(gl_log[layer*STATEN + s]);

    size_t base2 = ((size_t)b * SEQL + (size_t)c * CH) * STATEN + s;
    const float2* bu2 = (const float2*)g_bu;
    __half2*      st2 = (__half2*)g_st;

    {
        float sr = 0.f, si = 0.f;
        #pragma unroll 4
        for (int t = 0; t < CH; t++) {
            float2 u = bu2[base2 + (size_t)t * STATEN];
            float br = u.x * ga, bi = u.y * ga;
            float nr = fmaf(lre, sr, fmaf(-lim, si, br));
            float ni = fmaf(lre, si, fmaf( lim, sr, bi));
            sr = nr; si = ni;
        }
        se_r[c][sl] = sr; se_i[c][sl] = si;
    }
    __syncthreads();

    if (tid < 32) {
        float ar = lre, ai = lim;
        #pragma unroll
        for (int q = 0; q < LOG2CH; q++) {
            float nr = ar*ar - ai*ai;
            ai = 2.f * ar * ai;
            ar = nr;
        }
        float cr = 0.f, ci = 0.f;
        #pragma unroll
        for (int c2 = 0; c2 < NCH; c2++) {
            ca_r[c2][sl] = cr; ca_i[c2][sl] = ci;
            float er = se_r[c2][sl], ei = se_i[c2][sl];
            float nr = fmaf(ar, cr, fmaf(-ai, ci, er));
            float ni = fmaf(ar, ci, fmaf( ai, cr, ei));
            cr = nr; ci = ni;
        }
    }
    __syncthreads();

    {
        float sr = ca_r[c][sl], si = ca_i[c][sl];
        #pragma unroll 4
        for (int t = 0; t < CH; t++) {
            float2 u = bu2[base2 + (size_t)t * STATEN];
            float br = u.x * ga, bi = u.y * ga;
            float nr = fmaf(lre, sr, fmaf(-lim, si, br));
            float ni = fmaf(lre, si, fmaf( lim, sr, bi));
            sr = nr; si = ni;
            st2[base2 + (size_t)t * STATEN] = __floats2half2_rn(sr, si);
        }
    }
}

// ==================== driver ================================================
extern "C" void kernel_launch(void* const* d_in, const int* in_sizes, int n_in,
                              void* d_out, int out_size)
{
    (void)in_sizes; (void)n_in; (void)out_size;
    const float* x    = (const float*)d_in[0];
    const float* embW = (const float*)d_in[1];
    const float* embb = (const float*)d_in[2];
    const float* nu   = (const float*)d_in[3];
    const float* th   = (const float*)d_in[4];
    const float* gl   = (const float*)d_in[5];
    const float* Bre  = (const float*)d_in[6];
    const float* Bim  = (const float*)d_in[7];
    const float* Cre  = (const float*)d_in[8];
    const float* Cim  = (const float*)d_in[9];
    const float* Dv   = (const float*)d_in[10];
    const float* Wh   = (const float*)d_in[11];
    const float* bh   = (const float*)d_in[12];
    const float* Wo   = (const float*)d_in[13];
    const float* bo   = (const float*)d_in[14];
    const float* outW = (const float*)d_in[15];
    const float* outb = (const float*)d_in[16];
    float* out = (float*)d_out;

    __half *h, *y, *z, *xr, *wE, *wB, *wC, *wH, *wO, *wOut, *stp;
    float *bup;
    cudaGetSymbolAddress((void**)&h,    g_h);
    cudaGetSymbolAddress((void**)&y,    g_y);
    cudaGetSymbolAddress((void**)&z,    g_z);
    cudaGetSymbolAddress((void**)&xr,   g_xr);
    cudaGetSymbolAddress((void**)&wE,   g_wE);
    cudaGetSymbolAddress((void**)&wB,   g_wB);
    cudaGetSymbolAddress((void**)&wC,   g_wC);
    cudaGetSymbolAddress((void**)&wH,   g_wH);
    cudaGetSymbolAddress((void**)&wO,   g_wO);
    cudaGetSymbolAddress((void**)&wOut, g_wOut);
    cudaGetSymbolAddress((void**)&stp,  g_st);
    cudaGetSymbolAddress((void**)&bup,  g_bu);

    const int SM256 = NSTG*(BM+256)*HSTR*2;   // 122880
    const int SM128 = NSTG*(BM+128)*HSTR*2;   // 81920
    cudaFuncSetAttribute((const void*)gemm_h<256,__half>, cudaFuncAttributeMaxDynamicSharedMemorySize, SM256);
    cudaFuncSetAttribute((const void*)gemm_h<256,float>,  cudaFuncAttributeMaxDynamicSharedMemorySize, SM256);
    cudaFuncSetAttribute((const void*)gemm_h<128,float>,  cudaFuncAttributeMaxDynamicSharedMemorySize, SM128);

    dim3 tb(256);
    const int MB = M_TOT / BM;   // 256

    // ---- prep: fp16 conversion of input + weights ----
    to_half4<<<(M_TOT*INDIM/4+255)/256, tb>>>(xr, x, M_TOT*INDIM/4);
    to_half4<<<(HID*INDIM/4+255)/256, tb>>>(wE, embW, HID*INDIM/4);
    to_half4<<<(OUTD*HID/4+255)/256, tb>>>(wOut, outW, OUTD*HID/4);
    to_half4<<<(NLAYERS*MLPD*HID/4+255)/256, tb>>>(wH, Wh, NLAYERS*MLPD*HID/4);
    to_half4<<<(NLAYERS*HID*MLPD/4+255)/256, tb>>>(wO, Wo, NLAYERS*HID*MLPD/4);
    build_bcat<<<(NLAYERS*S2*HID)/256, tb>>>(Bre, Bim);
    build_ccat<<<(NLAYERS*HID*S2)/256, tb>>>(Cre, Cim);

    // embedding: h = half(x @ embW^T + embb)
    gemm_h<256,__half><<<dim3(HID/256, MB), tb, SM256>>>(M_TOT, HID, INDIM, xr, wE, embb, (const __half*)nullptr, h, 1);

    for (int l = 0; l < NLAYERS; l++) {
        // bu = h @ Bcat^T   [M, 512] fp32 (scan input unrounded)
        gemm_h<256,float><<<dim3(S2/256, MB), tb, SM256>>>(M_TOT, S2, HID, h, wB + (size_t)l*S2*HID,
                                                           (const float*)nullptr, (const float*)nullptr, bup, 0);
        // fused chunked complex scan
        scan_fused<<<dim3(STATEN/32, BATCHN), 1024>>>(nu, th, gl, l);

        // y = half([st interleaved] @ wC^T + D*h)
        gemm_h<256,__half><<<dim3(HID/256, MB), tb, SM256>>>(M_TOT, HID, S2, stp, wC + (size_t)l*HID*S2,
                                                             Dv + (size_t)l*HID, h, y, 7);
        // MLP
        gemm_h<256,__half><<<dim3(MLPD/256, MB), tb, SM256>>>(M_TOT, MLPD, HID, y, wH + (size_t)l*MLPD*HID,
                                                              bh + (size_t)l*MLPD, (const __half*)nullptr, z, 2);
        gemm_h<256,__half><<<dim3(HID/256, MB), tb, SM256>>>(M_TOT, HID, MLPD, z, wO + (size_t)l*HID*MLPD,
                                                             bo + (size_t)l*HID, y, h, 3);
    }

    // out = h @ outW^T + outb   (fp32 store)
    gemm_h<128,float><<<dim3(OUTD/128, MB), tb, SM128>>>(M_TOT, OUTD, HID, h, wOut, outb, (const float*)nullptr, out, 1);
}

// round 10
// speedup vs baseline: 3.2273x; 1.0316x over previous
#include <cuda_runtime.h>
#include <cuda_fp16.h>
#include <math.h>
#include <stdint.h>

#define BATCHN  16
#define SEQL    2048
#define INDIM   64
#define HID     256
#define STATEN  256
#define MLPD    1024
#define OUTD    128
#define NLAYERS 4
#define M_TOT   (BATCHN*SEQL)   /* 32768 */
#define CH      32
#define NCH     (SEQL/CH)       /* 64 */
#define LOG2CH  5
#define SGRP    16              /* states per scan block */
#define S2      (2*STATEN)      /* 512 */

// ---------------- scratch (static device globals) ---------------------------
__device__ __half g_h [M_TOT*HID];
__device__ __half g_y [M_TOT*HID];
__device__ float  g_bu[M_TOT*S2];        // interleaved: col 2s = re_s, 2s+1 = im_s
__device__ __half g_st[M_TOT*S2];        // interleaved likewise
__device__ __half g_z [M_TOT*MLPD];
__device__ __half g_xr  [M_TOT*INDIM];
__device__ __half g_wE  [HID*INDIM];
__device__ __half g_wB  [NLAYERS*S2*HID];   // row 2s=Bre[s], 2s+1=Bim[s]
__device__ __half g_wC  [NLAYERS*HID*S2];   // col 2s=Cre[.][s], 2s+1=-Cim[.][s]
__device__ __half g_wH  [NLAYERS*MLPD*HID];
__device__ __half g_wO  [NLAYERS*HID*MLPD];
__device__ __half g_wOut[OUTD*HID];

// ==================== FP16 tensor-core GEMM =================================
// C[M,N] = epi(A[M,K] @ W[N,K]^T); A,W fp16; accumulate fp32.
// epi: 0 raw | 1 +bias | 2 gelu(+bias) | 3 +bias+resid | 7 + bias[c]*resid
#define BM   128
#define BK   32            /* k elements per stage */
#define HSTR 40            /* padded row stride in halves (80B) — ldmatrix conflict-free */
#define NSTG 4

__device__ __forceinline__ void cp16(uint32_t dst, const void* src){
    asm volatile("cp.async.ca.shared.global [%0], [%1], 16;\n" :: "r"(dst), "l"(src));
}
__device__ __forceinline__ void mma_f16(float* c, const uint32_t* a, const uint32_t* b){
    asm volatile("mma.sync.aligned.m16n8k16.row.col.f32.f16.f16.f32 "
        "{%0,%1,%2,%3}, {%4,%5,%6,%7}, {%8,%9}, {%0,%1,%2,%3};"
        : "+f"(c[0]), "+f"(c[1]), "+f"(c[2]), "+f"(c[3])
        : "r"(a[0]), "r"(a[1]), "r"(a[2]), "r"(a[3]), "r"(b[0]), "r"(b[1]));
}
__device__ __forceinline__ void ldm4(uint32_t& r0, uint32_t& r1, uint32_t& r2, uint32_t& r3,
                                     uint32_t addr){
    asm volatile("ldmatrix.sync.aligned.m8n8.x4.shared.b16 {%0,%1,%2,%3}, [%4];"
        : "=r"(r0), "=r"(r1), "=r"(r2), "=r"(r3) : "r"(addr));
}

template<typename CT>
__device__ __forceinline__ void store2(CT* C, size_t off, float v0, float v1);
template<> __device__ __forceinline__ void store2<__half>(__half* C, size_t off, float v0, float v1){
    *(__half2*)(C + off) = __floats2half2_rn(v0, v1);
}
template<> __device__ __forceinline__ void store2<float>(float* C, size_t off, float v0, float v1){
    C[off] = v0; C[off+1] = v1;
}
template<typename CT>
__device__ __forceinline__ float rd(const CT* p, size_t off);
template<> __device__ __forceinline__ float rd<__half>(const __half* p, size_t off){ return __half2float(p[off]); }
template<> __device__ __forceinline__ float rd<float>(const float* p, size_t off){ return p[off]; }

template<int BN, typename CT>
__global__ __launch_bounds__(256)
void gemm_h(int M, int N, int K,
            const __half* __restrict__ A, const __half* __restrict__ W,
            const float* __restrict__ bias, const CT* __restrict__ resid,
            CT* __restrict__ C, int epi)
{
    constexpr int NT    = BN/32;                 // n fragments per warp (4 or 8)
    constexpr int NP    = NT/2;                  // B ldmatrix.x4 per ks (2 or 4)
    constexpr int NLB   = BN/64;                 // B cp16 iters per thread
    constexpr int SLOTA = BM*HSTR;               // halves
    constexpr int SLOTB = BN*HSTR;

    extern __shared__ __align__(16) __half smem[];
    __half* As = smem;
    __half* Bs = smem + NSTG*SLOTA;

    int tid  = threadIdx.x;
    int lane = tid & 31;
    int wid  = tid >> 5;
    int gr   = lane >> 2;
    int ct   = lane & 3;
    int wm   = (wid >> 2) * 64;
    int wn   = (wid & 3) * (BN/4);
    int row0 = blockIdx.y * BM;
    int col0 = blockIdx.x * BN;

    uint32_t sAb = (uint32_t)__cvta_generic_to_shared(As);
    uint32_t sBb = (uint32_t)__cvta_generic_to_shared(Bs);

    // ldmatrix per-lane base addresses (within stage 0)
    uint32_t aBase = sAb + (uint32_t)((wm + ((lane>>3)&1)*8 + (lane&7))*HSTR)*2
                   + (uint32_t)(lane>>4)*16;
    uint32_t bBase = sBb + (uint32_t)((wn + (lane>>4)*8 + (lane&7))*HSTR)*2
                   + (uint32_t)((lane>>3)&1)*16;

    float acc[4][NT][4];
    #pragma unroll
    for (int i=0;i<4;i++)
        #pragma unroll
        for (int j=0;j<NT;j++)
            #pragma unroll
            for (int q=0;q<4;q++) acc[i][j][q] = 0.f;

    int nk = K / BK;

    // guarded stage load: only touches memory when kt < nk; ALWAYS commits a
    // group so wait_group accounting stays consistent.
    auto load_stage = [&](int kt){
        if (kt < nk) {
            int slot = kt % NSTG;
            int k0 = kt * BK;
            #pragma unroll
            for (int j = 0; j < 2; j++) {
                int id = tid + j*256;
                int r = id >> 2, kb = id & 3;
                cp16(sAb + (slot*SLOTA + r*HSTR)*2 + kb*16,
                     A + (size_t)(row0 + r)*K + k0 + kb*8);
            }
            #pragma unroll
            for (int j = 0; j < NLB; j++) {
                int id = tid + j*256;
                int r = id >> 2, kb = id & 3;
                cp16(sBb + (slot*SLOTB + r*HSTR)*2 + kb*16,
                     W + (size_t)(col0 + r)*K + k0 + kb*8);
            }
        }
        asm volatile("cp.async.commit_group;\n");
    };

    load_stage(0);
    load_stage(1);
    load_stage(2);

    for (int kt = 0; kt < nk; kt++) {
        asm volatile("cp.async.wait_group 2;\n");
        __syncthreads();
        load_stage(kt + 3);

        int slot = kt % NSTG;
        uint32_t aSlot = aBase + slot*SLOTA*2;
        uint32_t bSlot = bBase + slot*SLOTB*2;
        #pragma unroll
        for (int ks = 0; ks < 2; ks++) {     // two k16 steps per stage
            uint32_t ua[4][4], ub[NT][2];
            #pragma unroll
            for (int mt = 0; mt < 4; mt++)
                ldm4(ua[mt][0], ua[mt][1], ua[mt][2], ua[mt][3],
                     aSlot + mt*16*HSTR*2 + ks*32);
            #pragma unroll
            for (int p = 0; p < NP; p++)
                ldm4(ub[2*p][0], ub[2*p][1], ub[2*p+1][0], ub[2*p+1][1],
                     bSlot + p*16*HSTR*2 + ks*32);
            #pragma unroll
            for (int mt = 0; mt < 4; mt++)
                #pragma unroll
                for (int nt = 0; nt < NT; nt++)
                    mma_f16(acc[mt][nt], ua[mt], ub[nt]);
        }
    }

    #pragma unroll
    for (int mt = 0; mt < 4; mt++) {
        #pragma unroll
        for (int half = 0; half < 2; half++) {
            int r = row0 + wm + mt*16 + gr + half*8;
            size_t ro = (size_t)r * N;
            #pragma unroll
            for (int nt = 0; nt < NT; nt++) {
                int cc = col0 + wn + nt*8 + ct*2;
                float v0 = acc[mt][nt][half*2 + 0];
                float v1 = acc[mt][nt][half*2 + 1];
                if (epi == 1) {
                    v0 += bias[cc]; v1 += bias[cc+1];
                } else if (epi == 2) {
                    float t0 = v0 + bias[cc], t1 = v1 + bias[cc+1];
                    v0 = 0.5f * t0 * (1.0f + erff(t0 * 0.70710678118654752f));
                    v1 = 0.5f * t1 * (1.0f + erff(t1 * 0.70710678118654752f));
                } else if (epi == 3) {
                    v0 += bias[cc]   + rd<CT>(resid, ro+cc);
                    v1 += bias[cc+1] + rd<CT>(resid, ro+cc+1);
                } else if (epi == 7) {
                    v0 += bias[cc]   * rd<CT>(resid, ro+cc);
                    v1 += bias[cc+1] * rd<CT>(resid, ro+cc+1);
                }
                store2<CT>(C, ro + cc, v0, v1);
            }
        }
    }
}

// ==================== unified prep kernel ===================================
// One launch: fp16-converts x + 4 weight sets, builds interleaved Bcat/Ccat.
__global__ void prep_all(const float* __restrict__ x,    const float* __restrict__ embW,
                         const float* __restrict__ outW, const float* __restrict__ Wh,
                         const float* __restrict__ Wo,   const float* __restrict__ Bre,
                         const float* __restrict__ Bim,  const float* __restrict__ Cre,
                         const float* __restrict__ Cim)
{
    const int N0 = M_TOT*INDIM/4;
    const int N1 = N0 + HID*INDIM/4;
    const int N2 = N1 + OUTD*HID/4;
    const int N3 = N2 + NLAYERS*MLPD*HID/4;
    const int N4 = N3 + NLAYERS*HID*MLPD/4;
    const int N5 = N4 + NLAYERS*S2*HID;
    const int N6 = N5 + NLAYERS*HID*S2;

    int i = blockIdx.x * blockDim.x + threadIdx.x;
    if (i < N4) {
        const float* src; __half* dst; int j;
        if (i < N0)      { src = x;    dst = g_xr;   j = i; }
        else if (i < N1) { src = embW; dst = g_wE;   j = i - N0; }
        else if (i < N2) { src = outW; dst = g_wOut; j = i - N1; }
        else if (i < N3) { src = Wh;   dst = g_wH;   j = i - N2; }
        else             { src = Wo;   dst = g_wO;   j = i - N3; }
        float4 v = ((const float4*)src)[j];
        ((__half2*)dst)[j*2]   = __floats2half2_rn(v.x, v.y);
        ((__half2*)dst)[j*2+1] = __floats2half2_rn(v.z, v.w);
    } else if (i < N5) {
        int j  = i - N4;
        int k  = j & (HID-1);
        int rr = (j >> 8) & (S2-1);
        int l  = j >> 17;
        int s  = rr >> 1;
        float v = (rr & 1) ? Bim[((size_t)l*STATEN + s)*HID + k]
                           : Bre[((size_t)l*STATEN + s)*HID + k];
        g_wB[j] = __float2half_rn(v);
    } else if (i < N6) {
        int j  = i - N5;
        int kk = j & (S2-1);
        int hh = (j >> 9) & (HID-1);
        int l  = j >> 17;
        int s  = kk >> 1;
        float v = (kk & 1) ? -Cim[((size_t)l*HID + hh)*STATEN + s]
                           :  Cre[((size_t)l*HID + hh)*STATEN + s];
        g_wC[j] = __float2half_rn(v);
    }
}
#define PREP_TOTAL (M_TOT*INDIM/4 + HID*INDIM/4 + OUTD*HID/4 + NLAYERS*MLPD*HID/4 \
                    + NLAYERS*HID*MLPD/4 + NLAYERS*S2*HID + NLAYERS*HID*S2)

// ==================== fused LRU scan ========================================
__device__ __forceinline__ void lam_of(const float* nu_log, const float* th_log,
                                       int layer, int s, float& lre, float& lim)
{
    float nu = nu_log[layer*STATEN + s];
    float th = th_log[layer*STATEN + s];
    float mag = expf(-expf(nu));
    float ang = expf(th);
    float sv, cv;
    sincosf(ang, &sv, &cv);
    lre = mag * cv;
    lim = mag * sv;
}

// grid: (STATEN/SGRP, BATCHN) = (16,16), block: 1024 = 64 chunks x 16 states
__global__ __launch_bounds__(1024)
void scan_fused(const float* __restrict__ nu_log, const float* __restrict__ th_log,
                const float* __restrict__ gl_log, int layer)
{
    __shared__ float se_r[NCH][SGRP], se_i[NCH][SGRP];
    __shared__ float ca_r[NCH][SGRP], ca_i[NCH][SGRP];

    int tid = threadIdx.x;
    int c   = tid >> 4;            // chunk 0..63
    int sl  = tid & (SGRP-1);      // state lane 0..15
    int s   = blockIdx.x * SGRP + sl;
    int b   = blockIdx.y;

    float lre, lim;
    lam_of(nu_log, th_log, layer, s, lre, lim);
    float ga = expf(gl_log[layer*STATEN + s]);

    size_t base2 = ((size_t)b * SEQL + (size_t)c * CH) * STATEN + s;
    const float2* bu2 = (const float2*)g_bu;
    __half2*      st2 = (__half2*)g_st;

    // phase 1: local scan, keep chunk-end state
    {
        float sr = 0.f, si = 0.f;
        #pragma unroll 4
        for (int t = 0; t < CH; t++) {
            float2 u = bu2[base2 + (size_t)t * STATEN];
            float br = u.x * ga, bi = u.y * ga;
            float nr = fmaf(lre, sr, fmaf(-lim, si, br));
            float ni = fmaf(lre, si, fmaf( lim, sr, bi));
            sr = nr; si = ni;
        }
        se_r[c][sl] = sr; se_i[c][sl] = si;
    }
    __syncthreads();

    // phase 2: serial carry combine (first SGRP threads; for them sl == tid)
    if (tid < SGRP) {
        float ar = lre, ai = lim;     // lam^CH via LOG2CH squarings
        #pragma unroll
        for (int q = 0; q < LOG2CH; q++) {
            float nr = ar*ar - ai*ai;
            ai = 2.f * ar * ai;
            ar = nr;
        }
        float cr = 0.f, ci = 0.f;
        #pragma unroll
        for (int c2 = 0; c2 < NCH; c2++) {
            ca_r[c2][sl] = cr; ca_i[c2][sl] = ci;
            float er = se_r[c2][sl], ei = se_i[c2][sl];
            float nr = fmaf(ar, cr, fmaf(-ai, ci, er));
            float ni = fmaf(ar, ci, fmaf( ai, cr, ei));
            cr = nr; ci = ni;
        }
    }
    __syncthreads();

    // phase 3: rescan with carry-in, write fp16 states
    {
        float sr = ca_r[c][sl], si = ca_i[c][sl];
        #pragma unroll 4
        for (int t = 0; t < CH; t++) {
            float2 u = bu2[base2 + (size_t)t * STATEN];
            float br = u.x * ga, bi = u.y * ga;
            float nr = fmaf(lre, sr, fmaf(-lim, si, br));
            float ni = fmaf(lre, si, fmaf( lim, sr, bi));
            sr = nr; si = ni;
            st2[base2 + (size_t)t * STATEN] = __floats2half2_rn(sr, si);
        }
    }
}

// ==================== driver ================================================
extern "C" void kernel_launch(void* const* d_in, const int* in_sizes, int n_in,
                              void* d_out, int out_size)
{
    (void)in_sizes; (void)n_in; (void)out_size;
    const float* x    = (const float*)d_in[0];
    const float* embW = (const float*)d_in[1];
    const float* embb = (const float*)d_in[2];
    const float* nu   = (const float*)d_in[3];
    const float* th   = (const float*)d_in[4];
    const float* gl   = (const float*)d_in[5];
    const float* Bre  = (const float*)d_in[6];
    const float* Bim  = (const float*)d_in[7];
    const float* Cre  = (const float*)d_in[8];
    const float* Cim  = (const float*)d_in[9];
    const float* Dv   = (const float*)d_in[10];
    const float* Wh   = (const float*)d_in[11];
    const float* bh   = (const float*)d_in[12];
    const float* Wo   = (const float*)d_in[13];
    const float* bo   = (const float*)d_in[14];
    const float* outW = (const float*)d_in[15];
    const float* outb = (const float*)d_in[16];
    float* out = (float*)d_out;

    __half *h, *y, *z, *xr, *wE, *wB, *wC, *wH, *wO, *wOut, *stp;
    float *bup;
    cudaGetSymbolAddress((void**)&h,    g_h);
    cudaGetSymbolAddress((void**)&y,    g_y);
    cudaGetSymbolAddress((void**)&z,    g_z);
    cudaGetSymbolAddress((void**)&xr,   g_xr);
    cudaGetSymbolAddress((void**)&wE,   g_wE);
    cudaGetSymbolAddress((void**)&wB,   g_wB);
    cudaGetSymbolAddress((void**)&wC,   g_wC);
    cudaGetSymbolAddress((void**)&wH,   g_wH);
    cudaGetSymbolAddress((void**)&wO,   g_wO);
    cudaGetSymbolAddress((void**)&wOut, g_wOut);
    cudaGetSymbolAddress((void**)&stp,  g_st);
    cudaGetSymbolAddress((void**)&bup,  g_bu);

    const int SM256 = NSTG*(BM+256)*HSTR*2;   // 122880
    const int SM128 = NSTG*(BM+128)*HSTR*2;   // 81920
    cudaFuncSetAttribute((const void*)gemm_h<256,__half>, cudaFuncAttributeMaxDynamicSharedMemorySize, SM256);
    cudaFuncSetAttribute((const void*)gemm_h<256,float>,  cudaFuncAttributeMaxDynamicSharedMemorySize, SM256);
    cudaFuncSetAttribute((const void*)gemm_h<128,float>,  cudaFuncAttributeMaxDynamicSharedMemorySize, SM128);

    dim3 tb(256);
    const int MB = M_TOT / BM;   // 256

    // ---- prep: ONE kernel for all conversions/concats ----
    prep_all<<<(PREP_TOTAL + 255)/256, tb>>>(x, embW, outW, Wh, Wo, Bre, Bim, Cre, Cim);

    // embedding: h = half(x @ embW^T + embb)
    gemm_h<256,__half><<<dim3(HID/256, MB), tb, SM256>>>(M_TOT, HID, INDIM, xr, wE, embb, (const __half*)nullptr, h, 1);

    for (int l = 0; l < NLAYERS; l++) {
        // bu = h @ Bcat^T   [M, 512] fp32 (scan input unrounded)
        gemm_h<256,float><<<dim3(S2/256, MB), tb, SM256>>>(M_TOT, S2, HID, h, wB + (size_t)l*S2*HID,
                                                           (const float*)nullptr, (const float*)nullptr, bup, 0);
        // fused chunked complex scan
        scan_fused<<<dim3(STATEN/SGRP, BATCHN), 1024>>>(nu, th, gl, l);

        // y = half([st interleaved] @ wC^T + D*h)
        gemm_h<256,__half><<<dim3(HID/256, MB), tb, SM256>>>(M_TOT, HID, S2, stp, wC + (size_t)l*HID*S2,
                                                             Dv + (size_t)l*HID, h, y, 7);
        // MLP
        gemm_h<256,__half><<<dim3(MLPD/256, MB), tb, SM256>>>(M_TOT, MLPD, HID, y, wH + (size_t)l*MLPD*HID,
                                                              bh + (size_t)l*MLPD, (const __half*)nullptr, z, 2);
        gemm_h<256,__half><<<dim3(HID/256, MB), tb, SM256>>>(M_TOT, HID, MLPD, z, wO + (size_t)l*HID*MLPD,
                                                             bo + (size_t)l*HID, y, h, 3);
    }

    // out = h @ outW^T + outb   (fp32 store)
    gemm_h<128,float><<<dim3(OUTD/128, MB), tb, SM128>>>(M_TOT, OUTD, HID, h, wOut, outb, (const float*)nullptr, out, 1);
}

// round 11
// speedup vs baseline: 3.3284x; 1.0313x over previous
#include <cuda_runtime.h>
#include <cuda_fp16.h>
#include <math.h>
#include <stdint.h>

#define BATCHN  16
#define SEQL    2048
#define INDIM   64
#define HID     256
#define STATEN  256
#define MLPD    1024
#define OUTD    128
#define NLAYERS 4
#define M_TOT   (BATCHN*SEQL)   /* 32768 */
#define CH      32
#define NCH     (SEQL/CH)       /* 64 */
#define LOG2CH  5
#define SGRP    16              /* states per scan block */
#define S2      (2*STATEN)      /* 512 */

// ---------------- scratch (static device globals) ---------------------------
__device__ __half g_h [M_TOT*HID];
__device__ __half g_y [M_TOT*HID];
__device__ float  g_bu[M_TOT*S2];        // interleaved: col 2s = re_s, 2s+1 = im_s
__device__ __half g_st[M_TOT*S2];        // interleaved likewise
__device__ __half g_z [M_TOT*MLPD];
__device__ __half g_xr  [M_TOT*INDIM];
__device__ __half g_wE  [HID*INDIM];
__device__ __half g_wB  [NLAYERS*S2*HID];   // row 2s=Bre[s]*ga, 2s+1=Bim[s]*ga
__device__ __half g_wC  [NLAYERS*HID*S2];   // col 2s=Cre[.][s], 2s+1=-Cim[.][s]
__device__ __half g_wH  [NLAYERS*MLPD*HID];
__device__ __half g_wO  [NLAYERS*HID*MLPD];
__device__ __half g_wOut[OUTD*HID];

// ==================== FP16 tensor-core GEMM =================================
// C[M,N] = epi(A[M,K] @ W[N,K]^T); A,W fp16; accumulate fp32.
// epi: 0 raw | 1 +bias | 2 gelu(+bias) | 3 +bias+resid | 7 + bias[c]*resid
#define BM   128
#define BK   32            /* k elements per stage */
#define HSTR 40            /* padded row stride in halves (80B) — ldmatrix conflict-free */
#define NSTG 4

__device__ __forceinline__ void cp16(uint32_t dst, const void* src){
    asm volatile("cp.async.ca.shared.global [%0], [%1], 16;\n" :: "r"(dst), "l"(src));
}
__device__ __forceinline__ void mma_f16(float* c, const uint32_t* a, const uint32_t* b){
    asm volatile("mma.sync.aligned.m16n8k16.row.col.f32.f16.f16.f32 "
        "{%0,%1,%2,%3}, {%4,%5,%6,%7}, {%8,%9}, {%0,%1,%2,%3};"
        : "+f"(c[0]), "+f"(c[1]), "+f"(c[2]), "+f"(c[3])
        : "r"(a[0]), "r"(a[1]), "r"(a[2]), "r"(a[3]), "r"(b[0]), "r"(b[1]));
}
__device__ __forceinline__ void ldm4(uint32_t& r0, uint32_t& r1, uint32_t& r2, uint32_t& r3,
                                     uint32_t addr){
    asm volatile("ldmatrix.sync.aligned.m8n8.x4.shared.b16 {%0,%1,%2,%3}, [%4];"
        : "=r"(r0), "=r"(r1), "=r"(r2), "=r"(r3) : "r"(addr));
}

template<typename CT>
__device__ __forceinline__ void store2(CT* C, size_t off, float v0, float v1);
template<> __device__ __forceinline__ void store2<__half>(__half* C, size_t off, float v0, float v1){
    *(__half2*)(C + off) = __floats2half2_rn(v0, v1);
}
template<> __device__ __forceinline__ void store2<float>(float* C, size_t off, float v0, float v1){
    C[off] = v0; C[off+1] = v1;
}
template<typename CT>
__device__ __forceinline__ float rd(const CT* p, size_t off);
template<> __device__ __forceinline__ float rd<__half>(const __half* p, size_t off){ return __half2float(p[off]); }
template<> __device__ __forceinline__ float rd<float>(const float* p, size_t off){ return p[off]; }

template<int BN, typename CT>
__global__ __launch_bounds__(256, (BN==128) ? 2 : 1)
void gemm_h(int M, int N, int K,
            const __half* __restrict__ A, const __half* __restrict__ W,
            const float* __restrict__ bias, const CT* __restrict__ resid,
            CT* __restrict__ C, int epi)
{
    constexpr int NT    = BN/32;                 // n fragments per warp (4 or 8)
    constexpr int NP    = NT/2;                  // B ldmatrix.x4 per ks (2 or 4)
    constexpr int NLB   = BN/64;                 // B cp16 iters per thread
    constexpr int SLOTA = BM*HSTR;               // halves
    constexpr int SLOTB = BN*HSTR;

    extern __shared__ __align__(16) __half smem[];
    __half* As = smem;
    __half* Bs = smem + NSTG*SLOTA;

    int tid  = threadIdx.x;
    int lane = tid & 31;
    int wid  = tid >> 5;
    int gr   = lane >> 2;
    int ct   = lane & 3;
    int wm   = (wid >> 2) * 64;
    int wn   = (wid & 3) * (BN/4);
    int row0 = blockIdx.y * BM;
    int col0 = blockIdx.x * BN;

    uint32_t sAb = (uint32_t)__cvta_generic_to_shared(As);
    uint32_t sBb = (uint32_t)__cvta_generic_to_shared(Bs);

    // ldmatrix per-lane base addresses (within stage 0)
    uint32_t aBase = sAb + (uint32_t)((wm + ((lane>>3)&1)*8 + (lane&7))*HSTR)*2
                   + (uint32_t)(lane>>4)*16;
    uint32_t bBase = sBb + (uint32_t)((wn + (lane>>4)*8 + (lane&7))*HSTR)*2
                   + (uint32_t)((lane>>3)&1)*16;

    float acc[4][NT][4];
    #pragma unroll
    for (int i=0;i<4;i++)
        #pragma unroll
        for (int j=0;j<NT;j++)
            #pragma unroll
            for (int q=0;q<4;q++) acc[i][j][q] = 0.f;

    int nk = K / BK;

    // guarded stage load: only touches memory when kt < nk; ALWAYS commits a
    // group so wait_group accounting stays consistent.
    auto load_stage = [&](int kt){
        if (kt < nk) {
            int slot = kt % NSTG;
            int k0 = kt * BK;
            #pragma unroll
            for (int j = 0; j < 2; j++) {
                int id = tid + j*256;
                int r = id >> 2, kb = id & 3;
                cp16(sAb + (slot*SLOTA + r*HSTR)*2 + kb*16,
                     A + (size_t)(row0 + r)*K + k0 + kb*8);
            }
            #pragma unroll
            for (int j = 0; j < NLB; j++) {
                int id = tid + j*256;
                int r = id >> 2, kb = id & 3;
                cp16(sBb + (slot*SLOTB + r*HSTR)*2 + kb*16,
                     W + (size_t)(col0 + r)*K + k0 + kb*8);
            }
        }
        asm volatile("cp.async.commit_group;\n");
    };

    load_stage(0);
    load_stage(1);
    load_stage(2);

    for (int kt = 0; kt < nk; kt++) {
        asm volatile("cp.async.wait_group 2;\n");
        __syncthreads();
        load_stage(kt + 3);

        int slot = kt % NSTG;
        uint32_t aSlot = aBase + slot*SLOTA*2;
        uint32_t bSlot = bBase + slot*SLOTB*2;
        #pragma unroll
        for (int ks = 0; ks < 2; ks++) {     // two k16 steps per stage
            uint32_t ua[4][4], ub[NT][2];
            #pragma unroll
            for (int mt = 0; mt < 4; mt++)
                ldm4(ua[mt][0], ua[mt][1], ua[mt][2], ua[mt][3],
                     aSlot + mt*16*HSTR*2 + ks*32);
            #pragma unroll
            for (int p = 0; p < NP; p++)
                ldm4(ub[2*p][0], ub[2*p][1], ub[2*p+1][0], ub[2*p+1][1],
                     bSlot + p*16*HSTR*2 + ks*32);
            #pragma unroll
            for (int mt = 0; mt < 4; mt++)
                #pragma unroll
                for (int nt = 0; nt < NT; nt++)
                    mma_f16(acc[mt][nt], ua[mt], ub[nt]);
        }
    }

    #pragma unroll
    for (int mt = 0; mt < 4; mt++) {
        #pragma unroll
        for (int half = 0; half < 2; half++) {
            int r = row0 + wm + mt*16 + gr + half*8;
            size_t ro = (size_t)r * N;
            #pragma unroll
            for (int nt = 0; nt < NT; nt++) {
                int cc = col0 + wn + nt*8 + ct*2;
                float v0 = acc[mt][nt][half*2 + 0];
                float v1 = acc[mt][nt][half*2 + 1];
                if (epi == 1) {
                    v0 += bias[cc]; v1 += bias[cc+1];
                } else if (epi == 2) {
                    float t0 = v0 + bias[cc], t1 = v1 + bias[cc+1];
                    v0 = 0.5f * t0 * (1.0f + erff(t0 * 0.70710678118654752f));
                    v1 = 0.5f * t1 * (1.0f + erff(t1 * 0.70710678118654752f));
                } else if (epi == 3) {
                    v0 += bias[cc]   + rd<CT>(resid, ro+cc);
                    v1 += bias[cc+1] + rd<CT>(resid, ro+cc+1);
                } else if (epi == 7) {
                    v0 += bias[cc]   * rd<CT>(resid, ro+cc);
                    v1 += bias[cc+1] * rd<CT>(resid, ro+cc+1);
                }
                store2<CT>(C, ro + cc, v0, v1);
            }
        }
    }
}

// ==================== unified prep kernel ===================================
// One launch: fp16-converts x + 4 weight sets, builds interleaved Bcat/Ccat.
// Bcat rows are pre-scaled by gamma = exp(gl) (per state).
__global__ void prep_all(const float* __restrict__ x,    const float* __restrict__ embW,
                         const float* __restrict__ outW, const float* __restrict__ Wh,
                         const float* __restrict__ Wo,   const float* __restrict__ Bre,
                         const float* __restrict__ Bim,  const float* __restrict__ Cre,
                         const float* __restrict__ Cim,  const float* __restrict__ gl)
{
    const int N0 = M_TOT*INDIM/4;
    const int N1 = N0 + HID*INDIM/4;
    const int N2 = N1 + OUTD*HID/4;
    const int N3 = N2 + NLAYERS*MLPD*HID/4;
    const int N4 = N3 + NLAYERS*HID*MLPD/4;
    const int N5 = N4 + NLAYERS*S2*HID;
    const int N6 = N5 + NLAYERS*HID*S2;

    int i = blockIdx.x * blockDim.x + threadIdx.x;
    if (i < N4) {
        const float* src; __half* dst; int j;
        if (i < N0)      { src = x;    dst = g_xr;   j = i; }
        else if (i < N1) { src = embW; dst = g_wE;   j = i - N0; }
        else if (i < N2) { src = outW; dst = g_wOut; j = i - N1; }
        else if (i < N3) { src = Wh;   dst = g_wH;   j = i - N2; }
        else             { src = Wo;   dst = g_wO;   j = i - N3; }
        float4 v = ((const float4*)src)[j];
        ((__half2*)dst)[j*2]   = __floats2half2_rn(v.x, v.y);
        ((__half2*)dst)[j*2+1] = __floats2half2_rn(v.z, v.w);
    } else if (i < N5) {
        int j  = i - N4;
        int k  = j & (HID-1);
        int rr = (j >> 8) & (S2-1);
        int l  = j >> 17;
        int s  = rr >> 1;
        float ga = expf(gl[l*STATEN + s]);
        float v = (rr & 1) ? Bim[((size_t)l*STATEN + s)*HID + k]
                           : Bre[((size_t)l*STATEN + s)*HID + k];
        g_wB[j] = __float2half_rn(v * ga);
    } else if (i < N6) {
        int j  = i - N5;
        int kk = j & (S2-1);
        int hh = (j >> 9) & (HID-1);
        int l  = j >> 17;
        int s  = kk >> 1;
        float v = (kk & 1) ? -Cim[((size_t)l*HID + hh)*STATEN + s]
                           :  Cre[((size_t)l*HID + hh)*STATEN + s];
        g_wC[j] = __float2half_rn(v);
    }
}
#define PREP_TOTAL (M_TOT*INDIM/4 + HID*INDIM/4 + OUTD*HID/4 + NLAYERS*MLPD*HID/4 \
                    + NLAYERS*HID*MLPD/4 + NLAYERS*S2*HID + NLAYERS*HID*S2)

// ==================== fused LRU scan ========================================
__device__ __forceinline__ void lam_of(const float* nu_log, const float* th_log,
                                       int layer, int s, float& lre, float& lim)
{
    float nu = nu_log[layer*STATEN + s];
    float th = th_log[layer*STATEN + s];
    float mag = expf(-expf(nu));
    float ang = expf(th);
    float sv, cv;
    sincosf(ang, &sv, &cv);
    lre = mag * cv;
    lim = mag * sv;
}

// grid: (STATEN/SGRP, BATCHN) = (16,16), block: 1024 = 64 chunks x 16 states
// (gamma already folded into wB, so bu is pre-scaled)
__global__ __launch_bounds__(1024)
void scan_fused(const float* __restrict__ nu_log, const float* __restrict__ th_log,
                int layer)
{
    __shared__ float se_r[NCH][SGRP], se_i[NCH][SGRP];
    __shared__ float ca_r[NCH][SGRP], ca_i[NCH][SGRP];

    int tid = threadIdx.x;
    int c   = tid >> 4;            // chunk 0..63
    int sl  = tid & (SGRP-1);      // state lane 0..15
    int s   = blockIdx.x * SGRP + sl;
    int b   = blockIdx.y;

    float lre, lim;
    lam_of(nu_log, th_log, layer, s, lre, lim);

    size_t base2 = ((size_t)b * SEQL + (size_t)c * CH) * STATEN + s;
    const float2* bu2 = (const float2*)g_bu;
    __half2*      st2 = (__half2*)g_st;

    // phase 1: local scan, keep chunk-end state
    {
        float sr = 0.f, si = 0.f;
        #pragma unroll 4
        for (int t = 0; t < CH; t++) {
            float2 u = bu2[base2 + (size_t)t * STATEN];
            float nr = fmaf(lre, sr, fmaf(-lim, si, u.x));
            float ni = fmaf(lre, si, fmaf( lim, sr, u.y));
            sr = nr; si = ni;
        }
        se_r[c][sl] = sr; se_i[c][sl] = si;
    }
    __syncthreads();

    // phase 2: serial carry combine (first SGRP threads; for them sl == tid)
    if (tid < SGRP) {
        float ar = lre, ai = lim;     // lam^CH via LOG2CH squarings
        #pragma unroll
        for (int q = 0; q < LOG2CH; q++) {
            float nr = ar*ar - ai*ai;
            ai = 2.f * ar * ai;
            ar = nr;
        }
        float cr = 0.f, ci = 0.f;
        #pragma unroll
        for (int c2 = 0; c2 < NCH; c2++) {
            ca_r[c2][sl] = cr; ca_i[c2][sl] = ci;
            float er = se_r[c2][sl], ei = se_i[c2][sl];
            float nr = fmaf(ar, cr, fmaf(-ai, ci, er));
            float ni = fmaf(ar, ci, fmaf( ai, cr, ei));
            cr = nr; ci = ni;
        }
    }
    __syncthreads();

    // phase 3: rescan with carry-in, write fp16 states
    {
        float sr = ca_r[c][sl], si = ca_i[c][sl];
        #pragma unroll 4
        for (int t = 0; t < CH; t++) {
            float2 u = bu2[base2 + (size_t)t * STATEN];
            float nr = fmaf(lre, sr, fmaf(-lim, si, u.x));
            float ni = fmaf(lre, si, fmaf( lim, sr, u.y));
            sr = nr; si = ni;
            st2[base2 + (size_t)t * STATEN] = __floats2half2_rn(sr, si);
        }
    }
}

// ==================== driver ================================================
extern "C" void kernel_launch(void* const* d_in, const int* in_sizes, int n_in,
                              void* d_out, int out_size)
{
    (void)in_sizes; (void)n_in; (void)out_size;
    const float* x    = (const float*)d_in[0];
    const float* embW = (const float*)d_in[1];
    const float* embb = (const float*)d_in[2];
    const float* nu   = (const float*)d_in[3];
    const float* th   = (const float*)d_in[4];
    const float* gl   = (const float*)d_in[5];
    const float* Bre  = (const float*)d_in[6];
    const float* Bim  = (const float*)d_in[7];
    const float* Cre  = (const float*)d_in[8];
    const float* Cim  = (const float*)d_in[9];
    const float* Dv   = (const float*)d_in[10];
    const float* Wh   = (const float*)d_in[11];
    const float* bh   = (const float*)d_in[12];
    const float* Wo   = (const float*)d_in[13];
    const float* bo   = (const float*)d_in[14];
    const float* outW = (const float*)d_in[15];
    const float* outb = (const float*)d_in[16];
    float* out = (float*)d_out;

    __half *h, *y, *z, *xr, *wE, *wB, *wC, *wH, *wO, *wOut, *stp;
    float *bup;
    cudaGetSymbolAddress((void**)&h,    g_h);
    cudaGetSymbolAddress((void**)&y,    g_y);
    cudaGetSymbolAddress((void**)&z,    g_z);
    cudaGetSymbolAddress((void**)&xr,   g_xr);
    cudaGetSymbolAddress((void**)&wE,   g_wE);
    cudaGetSymbolAddress((void**)&wB,   g_wB);
    cudaGetSymbolAddress((void**)&wC,   g_wC);
    cudaGetSymbolAddress((void**)&wH,   g_wH);
    cudaGetSymbolAddress((void**)&wO,   g_wO);
    cudaGetSymbolAddress((void**)&wOut, g_wOut);
    cudaGetSymbolAddress((void**)&stp,  g_st);
    cudaGetSymbolAddress((void**)&bup,  g_bu);

    const int SM256 = NSTG*(BM+256)*HSTR*2;   // 122880
    const int SM128 = NSTG*(BM+128)*HSTR*2;   // 81920
    cudaFuncSetAttribute((const void*)gemm_h<256,__half>, cudaFuncAttributeMaxDynamicSharedMemorySize, SM256);
    cudaFuncSetAttribute((const void*)gemm_h<128,__half>, cudaFuncAttributeMaxDynamicSharedMemorySize, SM128);
    cudaFuncSetAttribute((const void*)gemm_h<128,float>,  cudaFuncAttributeMaxDynamicSharedMemorySize, SM128);

    dim3 tb(256);
    const int MB = M_TOT / BM;   // 256

    // ---- prep: ONE kernel for all conversions/concats (gamma folded) ----
    prep_all<<<(PREP_TOTAL + 255)/256, tb>>>(x, embW, outW, Wh, Wo, Bre, Bim, Cre, Cim, gl);

    // embedding: h = half(x @ embW^T + embb)
    gemm_h<128,__half><<<dim3(HID/128, MB), tb, SM128>>>(M_TOT, HID, INDIM, xr, wE, embb, (const __half*)nullptr, h, 1);

    for (int l = 0; l < NLAYERS; l++) {
        // bu = h @ Bcat^T   [M, 512] fp32 (scan input unrounded; gamma pre-applied)
        gemm_h<128,float><<<dim3(S2/128, MB), tb, SM128>>>(M_TOT, S2, HID, h, wB + (size_t)l*S2*HID,
                                                           (const float*)nullptr, (const float*)nullptr, bup, 0);
        // fused chunked complex scan
        scan_fused<<<dim3(STATEN/SGRP, BATCHN), 1024>>>(nu, th, l);

        // y = half([st interleaved] @ wC^T + D*h)
        gemm_h<128,__half><<<dim3(HID/128, MB), tb, SM128>>>(M_TOT, HID, S2, stp, wC + (size_t)l*HID*S2,
                                                             Dv + (size_t)l*HID, h, y, 7);
        // MLP
        gemm_h<256,__half><<<dim3(MLPD/256, MB), tb, SM256>>>(M_TOT, MLPD, HID, y, wH + (size_t)l*MLPD*HID,
                                                              bh + (size_t)l*MLPD, (const __half*)nullptr, z, 2);
        gemm_h<128,__half><<<dim3(HID/128, MB), tb, SM128>>>(M_TOT, HID, MLPD, z, wO + (size_t)l*HID*MLPD,
                                                             bo + (size_t)l*HID, y, h, 3);
    }

    // out = h @ outW^T + outb   (fp32 store)
    gemm_h<128,float><<<dim3(OUTD/128, MB), tb, SM128>>>(M_TOT, OUTD, HID, h, wOut, outb, (const float*)nullptr, out, 1);
}

// round 12
// speedup vs baseline: 3.3585x; 1.0091x over previous
#include <cuda_runtime.h>
#include <cuda_fp16.h>
#include <math.h>
#include <stdint.h>

#define BATCHN  16
#define SEQL    2048
#define INDIM   64
#define HID     256
#define STATEN  256
#define MLPD    1024
#define OUTD    128
#define NLAYERS 4
#define M_TOT   (BATCHN*SEQL)   /* 32768 */
#define CH      32
#define NCH     (SEQL/CH)       /* 64 */
#define LOG2CH  5
#define SGRP    16              /* states per scan block */
#define S2      (2*STATEN)      /* 512 */

// ---------------- scratch (static device globals) ---------------------------
__device__ __half g_h [M_TOT*HID];
__device__ __half g_y [M_TOT*HID];
__device__ float  g_bu[M_TOT*S2];        // interleaved: col 2s = re_s, 2s+1 = im_s
__device__ __half g_st[M_TOT*S2];        // interleaved likewise
__device__ __half g_z [M_TOT*MLPD];
__device__ __half g_xr  [M_TOT*INDIM];
__device__ __half g_wE  [HID*INDIM];
__device__ __half g_wB  [NLAYERS*S2*HID];   // row 2s=Bre[s]*ga, 2s+1=Bim[s]*ga
__device__ __half g_wC  [NLAYERS*HID*S2];   // col 2s=Cre[.][s], 2s+1=-Cim[.][s]
__device__ __half g_wH  [NLAYERS*MLPD*HID];
__device__ __half g_wO  [NLAYERS*HID*MLPD];
__device__ __half g_wOut[OUTD*HID];

// ==================== FP16 tensor-core GEMM =================================
// C[M,N] = epi(A[M,K] @ W[N,K]^T); A,W fp16; accumulate fp32.
// epi: 0 raw | 1 +bias | 2 gelu(+bias) | 3 +bias+resid | 7 + bias[c]*resid
#define BM   128
#define BK   32            /* k elements per stage */
#define HSTR 40            /* padded row stride in halves (80B) — ldmatrix conflict-free */
#define NSTG 4

__device__ __forceinline__ void cp16(uint32_t dst, const void* src){
    asm volatile("cp.async.ca.shared.global [%0], [%1], 16;\n" :: "r"(dst), "l"(src));
}
__device__ __forceinline__ void mma_f16(float* c, const uint32_t* a, const uint32_t* b){
    asm volatile("mma.sync.aligned.m16n8k16.row.col.f32.f16.f16.f32 "
        "{%0,%1,%2,%3}, {%4,%5,%6,%7}, {%8,%9}, {%0,%1,%2,%3};"
        : "+f"(c[0]), "+f"(c[1]), "+f"(c[2]), "+f"(c[3])
        : "r"(a[0]), "r"(a[1]), "r"(a[2]), "r"(a[3]), "r"(b[0]), "r"(b[1]));
}
__device__ __forceinline__ void ldm4(uint32_t& r0, uint32_t& r1, uint32_t& r2, uint32_t& r3,
                                     uint32_t addr){
    asm volatile("ldmatrix.sync.aligned.m8n8.x4.shared.b16 {%0,%1,%2,%3}, [%4];"
        : "=r"(r0), "=r"(r1), "=r"(r2), "=r"(r3) : "r"(addr));
}

template<typename CT>
__device__ __forceinline__ void store2(CT* C, size_t off, float v0, float v1);
template<> __device__ __forceinline__ void store2<__half>(__half* C, size_t off, float v0, float v1){
    *(__half2*)(C + off) = __floats2half2_rn(v0, v1);
}
template<> __device__ __forceinline__ void store2<float>(float* C, size_t off, float v0, float v1){
    C[off] = v0; C[off+1] = v1;
}
template<typename CT>
__device__ __forceinline__ float rd(const CT* p, size_t off);
template<> __device__ __forceinline__ float rd<__half>(const __half* p, size_t off){ return __half2float(p[off]); }
template<> __device__ __forceinline__ float rd<float>(const float* p, size_t off){ return p[off]; }

template<int BN, typename CT>
__global__ __launch_bounds__(256, (BN==128) ? 2 : 1)
void gemm_h(int M, int N, int K,
            const __half* __restrict__ A, const __half* __restrict__ W,
            const float* __restrict__ bias, const CT* __restrict__ resid,
            CT* __restrict__ C, int epi)
{
    constexpr int NT    = BN/32;                 // n fragments per warp (4 or 8)
    constexpr int NP    = NT/2;                  // B ldmatrix.x4 per ks (2 or 4)
    constexpr int NLB   = BN/64;                 // B cp16 iters per thread
    constexpr int SLOTA = BM*HSTR;               // halves
    constexpr int SLOTB = BN*HSTR;

    extern __shared__ __align__(16) __half smem[];
    __half* As = smem;
    __half* Bs = smem + NSTG*SLOTA;

    int tid  = threadIdx.x;
    int lane = tid & 31;
    int wid  = tid >> 5;
    int gr   = lane >> 2;
    int ct   = lane & 3;
    int wm   = (wid >> 2) * 64;
    int wn   = (wid & 3) * (BN/4);
    int row0 = blockIdx.y * BM;
    int col0 = blockIdx.x * BN;

    uint32_t sAb = (uint32_t)__cvta_generic_to_shared(As);
    uint32_t sBb = (uint32_t)__cvta_generic_to_shared(Bs);

    // ldmatrix per-lane base addresses (within stage 0)
    uint32_t aBase = sAb + (uint32_t)((wm + ((lane>>3)&1)*8 + (lane&7))*HSTR)*2
                   + (uint32_t)(lane>>4)*16;
    uint32_t bBase = sBb + (uint32_t)((wn + (lane>>4)*8 + (lane&7))*HSTR)*2
                   + (uint32_t)((lane>>3)&1)*16;

    float acc[4][NT][4];
    #pragma unroll
    for (int i=0;i<4;i++)
        #pragma unroll
        for (int j=0;j<NT;j++)
            #pragma unroll
            for (int q=0;q<4;q++) acc[i][j][q] = 0.f;

    int nk = K / BK;

    // guarded stage load: only touches memory when kt < nk; ALWAYS commits a
    // group so wait_group accounting stays consistent.
    auto load_stage = [&](int kt){
        if (kt < nk) {
            int slot = kt % NSTG;
            int k0 = kt * BK;
            #pragma unroll
            for (int j = 0; j < 2; j++) {
                int id = tid + j*256;
                int r = id >> 2, kb = id & 3;
                cp16(sAb + (slot*SLOTA + r*HSTR)*2 + kb*16,
                     A + (size_t)(row0 + r)*K + k0 + kb*8);
            }
            #pragma unroll
            for (int j = 0; j < NLB; j++) {
                int id = tid + j*256;
                int r = id >> 2, kb = id & 3;
                cp16(sBb + (slot*SLOTB + r*HSTR)*2 + kb*16,
                     W + (size_t)(col0 + r)*K + k0 + kb*8);
            }
        }
        asm volatile("cp.async.commit_group;\n");
    };

    load_stage(0);
    load_stage(1);
    load_stage(2);

    for (int kt = 0; kt < nk; kt++) {
        asm volatile("cp.async.wait_group 2;\n");
        __syncthreads();
        load_stage(kt + 3);

        int slot = kt % NSTG;
        uint32_t aSlot = aBase + slot*SLOTA*2;
        uint32_t bSlot = bBase + slot*SLOTB*2;
        #pragma unroll
        for (int ks = 0; ks < 2; ks++) {     // two k16 steps per stage
            uint32_t ua[4][4], ub[NT][2];
            #pragma unroll
            for (int mt = 0; mt < 4; mt++)
                ldm4(ua[mt][0], ua[mt][1], ua[mt][2], ua[mt][3],
                     aSlot + mt*16*HSTR*2 + ks*32);
            #pragma unroll
            for (int p = 0; p < NP; p++)
                ldm4(ub[2*p][0], ub[2*p][1], ub[2*p+1][0], ub[2*p+1][1],
                     bSlot + p*16*HSTR*2 + ks*32);
            #pragma unroll
            for (int mt = 0; mt < 4; mt++)
                #pragma unroll
                for (int nt = 0; nt < NT; nt++)
                    mma_f16(acc[mt][nt], ua[mt], ub[nt]);
        }
    }

    #pragma unroll
    for (int mt = 0; mt < 4; mt++) {
        #pragma unroll
        for (int half = 0; half < 2; half++) {
            int r = row0 + wm + mt*16 + gr + half*8;
            size_t ro = (size_t)r * N;
            #pragma unroll
            for (int nt = 0; nt < NT; nt++) {
                int cc = col0 + wn + nt*8 + ct*2;
                float v0 = acc[mt][nt][half*2 + 0];
                float v1 = acc[mt][nt][half*2 + 1];
                if (epi == 1) {
                    v0 += bias[cc]; v1 += bias[cc+1];
                } else if (epi == 2) {
                    float t0 = v0 + bias[cc], t1 = v1 + bias[cc+1];
                    v0 = 0.5f * t0 * (1.0f + erff(t0 * 0.70710678118654752f));
                    v1 = 0.5f * t1 * (1.0f + erff(t1 * 0.70710678118654752f));
                } else if (epi == 3) {
                    v0 += bias[cc]   + rd<CT>(resid, ro+cc);
                    v1 += bias[cc+1] + rd<CT>(resid, ro+cc+1);
                } else if (epi == 7) {
                    v0 += bias[cc]   * rd<CT>(resid, ro+cc);
                    v1 += bias[cc+1] * rd<CT>(resid, ro+cc+1);
                }
                store2<CT>(C, ro + cc, v0, v1);
            }
        }
    }
}

// ==================== unified prep kernel ===================================
// One launch: fp16-converts x + 4 weight sets, builds interleaved Bcat/Ccat.
// Bcat rows are pre-scaled by gamma = exp(gl) (per state).
__global__ void prep_all(const float* __restrict__ x,    const float* __restrict__ embW,
                         const float* __restrict__ outW, const float* __restrict__ Wh,
                         const float* __restrict__ Wo,   const float* __restrict__ Bre,
                         const float* __restrict__ Bim,  const float* __restrict__ Cre,
                         const float* __restrict__ Cim,  const float* __restrict__ gl)
{
    const int N0 = M_TOT*INDIM/4;
    const int N1 = N0 + HID*INDIM/4;
    const int N2 = N1 + OUTD*HID/4;
    const int N3 = N2 + NLAYERS*MLPD*HID/4;
    const int N4 = N3 + NLAYERS*HID*MLPD/4;
    const int N5 = N4 + NLAYERS*S2*HID;
    const int N6 = N5 + NLAYERS*HID*S2;

    int i = blockIdx.x * blockDim.x + threadIdx.x;
    if (i < N4) {
        const float* src; __half* dst; int j;
        if (i < N0)      { src = x;    dst = g_xr;   j = i; }
        else if (i < N1) { src = embW; dst = g_wE;   j = i - N0; }
        else if (i < N2) { src = outW; dst = g_wOut; j = i - N1; }
        else if (i < N3) { src = Wh;   dst = g_wH;   j = i - N2; }
        else             { src = Wo;   dst = g_wO;   j = i - N3; }
        float4 v = ((const float4*)src)[j];
        ((__half2*)dst)[j*2]   = __floats2half2_rn(v.x, v.y);
        ((__half2*)dst)[j*2+1] = __floats2half2_rn(v.z, v.w);
    } else if (i < N5) {
        int j  = i - N4;
        int k  = j & (HID-1);
        int rr = (j >> 8) & (S2-1);
        int l  = j >> 17;
        int s  = rr >> 1;
        float ga = expf(gl[l*STATEN + s]);
        float v = (rr & 1) ? Bim[((size_t)l*STATEN + s)*HID + k]
                           : Bre[((size_t)l*STATEN + s)*HID + k];
        g_wB[j] = __float2half_rn(v * ga);
    } else if (i < N6) {
        int j  = i - N5;
        int kk = j & (S2-1);
        int hh = (j >> 9) & (HID-1);
        int l  = j >> 17;
        int s  = kk >> 1;
        float v = (kk & 1) ? -Cim[((size_t)l*HID + hh)*STATEN + s]
                           :  Cre[((size_t)l*HID + hh)*STATEN + s];
        g_wC[j] = __float2half_rn(v);
    }
}
#define PREP_TOTAL (M_TOT*INDIM/4 + HID*INDIM/4 + OUTD*HID/4 + NLAYERS*MLPD*HID/4 \
                    + NLAYERS*HID*MLPD/4 + NLAYERS*S2*HID + NLAYERS*HID*S2)

// ==================== fused LRU scan ========================================
__device__ __forceinline__ void lam_of(const float* nu_log, const float* th_log,
                                       int layer, int s, float& lre, float& lim)
{
    float nu = nu_log[layer*STATEN + s];
    float th = th_log[layer*STATEN + s];
    float mag = expf(-expf(nu));
    float ang = expf(th);
    float sv, cv;
    sincosf(ang, &sv, &cv);
    lre = mag * cv;
    lim = mag * sv;
}

// grid: (STATEN/SGRP, BATCHN) = (16,16), block: 1024 = 64 chunks x 16 states
// (gamma already folded into wB, so bu is pre-scaled)
__global__ __launch_bounds__(1024)
void scan_fused(const float* __restrict__ nu_log, const float* __restrict__ th_log,
                int layer)
{
    __shared__ float se_r[NCH][SGRP], se_i[NCH][SGRP];
    __shared__ float ca_r[NCH][SGRP], ca_i[NCH][SGRP];

    int tid = threadIdx.x;
    int c   = tid >> 4;            // chunk 0..63
    int sl  = tid & (SGRP-1);      // state lane 0..15
    int s   = blockIdx.x * SGRP + sl;
    int b   = blockIdx.y;

    float lre, lim;
    lam_of(nu_log, th_log, layer, s, lre, lim);

    size_t base2 = ((size_t)b * SEQL + (size_t)c * CH) * STATEN + s;
    const float2* bu2 = (const float2*)g_bu;
    __half2*      st2 = (__half2*)g_st;

    // phase 1: local scan, keep chunk-end state
    {
        float sr = 0.f, si = 0.f;
        #pragma unroll 4
        for (int t = 0; t < CH; t++) {
            float2 u = bu2[base2 + (size_t)t * STATEN];
            float nr = fmaf(lre, sr, fmaf(-lim, si, u.x));
            float ni = fmaf(lre, si, fmaf( lim, sr, u.y));
            sr = nr; si = ni;
        }
        se_r[c][sl] = sr; se_i[c][sl] = si;
    }
    __syncthreads();

    // phase 2: serial carry combine (first SGRP threads; for them sl == tid)
    if (tid < SGRP) {
        float ar = lre, ai = lim;     // lam^CH via LOG2CH squarings
        #pragma unroll
        for (int q = 0; q < LOG2CH; q++) {
            float nr = ar*ar - ai*ai;
            ai = 2.f * ar * ai;
            ar = nr;
        }
        float cr = 0.f, ci = 0.f;
        #pragma unroll
        for (int c2 = 0; c2 < NCH; c2++) {
            ca_r[c2][sl] = cr; ca_i[c2][sl] = ci;
            float er = se_r[c2][sl], ei = se_i[c2][sl];
            float nr = fmaf(ar, cr, fmaf(-ai, ci, er));
            float ni = fmaf(ar, ci, fmaf( ai, cr, ei));
            cr = nr; ci = ni;
        }
    }
    __syncthreads();

    // phase 3: rescan with carry-in, write fp16 states
    {
        float sr = ca_r[c][sl], si = ca_i[c][sl];
        #pragma unroll 4
        for (int t = 0; t < CH; t++) {
            float2 u = bu2[base2 + (size_t)t * STATEN];
            float nr = fmaf(lre, sr, fmaf(-lim, si, u.x));
            float ni = fmaf(lre, si, fmaf( lim, sr, u.y));
            sr = nr; si = ni;
            st2[base2 + (size_t)t * STATEN] = __floats2half2_rn(sr, si);
        }
    }
}

// ==================== driver ================================================
extern "C" void kernel_launch(void* const* d_in, const int* in_sizes, int n_in,
                              void* d_out, int out_size)
{
    (void)in_sizes; (void)n_in; (void)out_size;
    const float* x    = (const float*)d_in[0];
    const float* embW = (const float*)d_in[1];
    const float* embb = (const float*)d_in[2];
    const float* nu   = (const float*)d_in[3];
    const float* th   = (const float*)d_in[4];
    const float* gl   = (const float*)d_in[5];
    const float* Bre  = (const float*)d_in[6];
    const float* Bim  = (const float*)d_in[7];
    const float* Cre  = (const float*)d_in[8];
    const float* Cim  = (const float*)d_in[9];
    const float* Dv   = (const float*)d_in[10];
    const float* Wh   = (const float*)d_in[11];
    const float* bh   = (const float*)d_in[12];
    const float* Wo   = (const float*)d_in[13];
    const float* bo   = (const float*)d_in[14];
    const float* outW = (const float*)d_in[15];
    const float* outb = (const float*)d_in[16];
    float* out = (float*)d_out;

    __half *h, *y, *z, *xr, *wE, *wB, *wC, *wH, *wO, *wOut, *stp;
    float *bup;
    cudaGetSymbolAddress((void**)&h,    g_h);
    cudaGetSymbolAddress((void**)&y,    g_y);
    cudaGetSymbolAddress((void**)&z,    g_z);
    cudaGetSymbolAddress((void**)&xr,   g_xr);
    cudaGetSymbolAddress((void**)&wE,   g_wE);
    cudaGetSymbolAddress((void**)&wB,   g_wB);
    cudaGetSymbolAddress((void**)&wC,   g_wC);
    cudaGetSymbolAddress((void**)&wH,   g_wH);
    cudaGetSymbolAddress((void**)&wO,   g_wO);
    cudaGetSymbolAddress((void**)&wOut, g_wOut);
    cudaGetSymbolAddress((void**)&stp,  g_st);
    cudaGetSymbolAddress((void**)&bup,  g_bu);

    const int SM128 = NSTG*(BM+128)*HSTR*2;   // 81920
    cudaFuncSetAttribute((const void*)gemm_h<128,__half>, cudaFuncAttributeMaxDynamicSharedMemorySize, SM128);
    cudaFuncSetAttribute((const void*)gemm_h<128,float>,  cudaFuncAttributeMaxDynamicSharedMemorySize, SM128);

    dim3 tb(256);
    const int MB = M_TOT / BM;   // 256

    // ---- prep: ONE kernel for all conversions/concats (gamma folded) ----
    prep_all<<<(PREP_TOTAL + 255)/256, tb>>>(x, embW, outW, Wh, Wo, Bre, Bim, Cre, Cim, gl);

    // embedding: h = half(x @ embW^T + embb)
    gemm_h<128,__half><<<dim3(HID/128, MB), tb, SM128>>>(M_TOT, HID, INDIM, xr, wE, embb, (const __half*)nullptr, h, 1);

    for (int l = 0; l < NLAYERS; l++) {
        // bu = h @ Bcat^T   [M, 512] fp32 (scan input unrounded; gamma pre-applied)
        gemm_h<128,float><<<dim3(S2/128, MB), tb, SM128>>>(M_TOT, S2, HID, h, wB + (size_t)l*S2*HID,
                                                           (const float*)nullptr, (const float*)nullptr, bup, 0);
        // fused chunked complex scan
        scan_fused<<<dim3(STATEN/SGRP, BATCHN), 1024>>>(nu, th, l);

        // y = half([st interleaved] @ wC^T + D*h)
        gemm_h<128,__half><<<dim3(HID/128, MB), tb, SM128>>>(M_TOT, HID, S2, stp, wC + (size_t)l*HID*S2,
                                                             Dv + (size_t)l*HID, h, y, 7);
        // MLP (Wh now BN=128, 2 CTAs/SM)
        gemm_h<128,__half><<<dim3(MLPD/128, MB), tb, SM128>>>(M_TOT, MLPD, HID, y, wH + (size_t)l*MLPD*HID,
                                                              bh + (size_t)l*MLPD, (const __half*)nullptr, z, 2);
        gemm_h<128,__half><<<dim3(HID/128, MB), tb, SM128>>>(M_TOT, HID, MLPD, z, wO + (size_t)l*HID*MLPD,
                                                             bo + (size_t)l*HID, y, h, 3);
    }

    // out = h @ outW^T + outb   (fp32 store)
    gemm_h<128,float><<<dim3(OUTD/128, MB), tb, SM128>>>(M_TOT, OUTD, HID, h, wOut, outb, (const float*)nullptr, out, 1);
}

// round 13
// speedup vs baseline: 3.5541x; 1.0583x over previous
#include <cuda_runtime.h>
#include <cuda_fp16.h>
#include <math.h>
#include <stdint.h>

#define BATCHN  16
#define SEQL    2048
#define INDIM   64
#define HID     256
#define STATEN  256
#define MLPD    1024
#define OUTD    128
#define NLAYERS 4
#define M_TOT   (BATCHN*SEQL)   /* 32768 */
#define CH      32
#define NCH     (SEQL/CH)       /* 64 */
#define LOG2CH  5
#define SGRP    16              /* states per scan block */
#define S2      (2*STATEN)      /* 512 */

// ---------------- scratch (static device globals) ---------------------------
__device__ __half g_h [M_TOT*HID];
__device__ __half g_y [M_TOT*HID];
__device__ __half g_bu[M_TOT*S2];        // interleaved: col 2s = re_s, 2s+1 = im_s (fp16)
__device__ __half g_st[M_TOT*S2];        // interleaved likewise
__device__ __half g_z [M_TOT*MLPD];
__device__ __half g_xr  [M_TOT*INDIM];
__device__ __half g_wE  [HID*INDIM];
__device__ __half g_wB  [NLAYERS*S2*HID];   // row 2s=Bre[s]*ga, 2s+1=Bim[s]*ga
__device__ __half g_wC  [NLAYERS*HID*S2];   // col 2s=Cre[.][s], 2s+1=-Cim[.][s]
__device__ __half g_wH  [NLAYERS*MLPD*HID];
__device__ __half g_wO  [NLAYERS*HID*MLPD];
__device__ __half g_wOut[OUTD*HID];

// ==================== FP16 tensor-core GEMM =================================
// C[M,N] = epi(A[M,K] @ W[N,K]^T); A,W fp16; accumulate fp32.
// epi: 0 raw | 1 +bias | 2 gelu(+bias) | 3 +bias+resid | 7 + bias[c]*resid
#define BM   128
#define BK   32            /* k elements per stage */
#define HSTR 40            /* padded row stride in halves (80B) — ldmatrix conflict-free */
#define NSTG 4

__device__ __forceinline__ void cp16(uint32_t dst, const void* src){
    asm volatile("cp.async.ca.shared.global [%0], [%1], 16;\n" :: "r"(dst), "l"(src));
}
__device__ __forceinline__ void mma_f16(float* c, const uint32_t* a, const uint32_t* b){
    asm volatile("mma.sync.aligned.m16n8k16.row.col.f32.f16.f16.f32 "
        "{%0,%1,%2,%3}, {%4,%5,%6,%7}, {%8,%9}, {%0,%1,%2,%3};"
        : "+f"(c[0]), "+f"(c[1]), "+f"(c[2]), "+f"(c[3])
        : "r"(a[0]), "r"(a[1]), "r"(a[2]), "r"(a[3]), "r"(b[0]), "r"(b[1]));
}
__device__ __forceinline__ void ldm4(uint32_t& r0, uint32_t& r1, uint32_t& r2, uint32_t& r3,
                                     uint32_t addr){
    asm volatile("ldmatrix.sync.aligned.m8n8.x4.shared.b16 {%0,%1,%2,%3}, [%4];"
        : "=r"(r0), "=r"(r1), "=r"(r2), "=r"(r3) : "r"(addr));
}

template<typename CT>
__device__ __forceinline__ void store2(CT* C, size_t off, float v0, float v1);
template<> __device__ __forceinline__ void store2<__half>(__half* C, size_t off, float v0, float v1){
    *(__half2*)(C + off) = __floats2half2_rn(v0, v1);
}
template<> __device__ __forceinline__ void store2<float>(float* C, size_t off, float v0, float v1){
    C[off] = v0; C[off+1] = v1;
}
template<typename CT>
__device__ __forceinline__ float rd(const CT* p, size_t off);
template<> __device__ __forceinline__ float rd<__half>(const __half* p, size_t off){ return __half2float(p[off]); }
template<> __device__ __forceinline__ float rd<float>(const float* p, size_t off){ return p[off]; }

template<int BN, typename CT>
__global__ __launch_bounds__(256, (BN==128) ? 2 : 1)
void gemm_h(int M, int N, int K,
            const __half* __restrict__ A, const __half* __restrict__ W,
            const float* __restrict__ bias, const CT* __restrict__ resid,
            CT* __restrict__ C, int epi)
{
    constexpr int NT    = BN/32;                 // n fragments per warp (4 or 8)
    constexpr int NP    = NT/2;                  // B ldmatrix.x4 per ks (2 or 4)
    constexpr int NLB   = BN/64;                 // B cp16 iters per thread
    constexpr int SLOTA = BM*HSTR;               // halves
    constexpr int SLOTB = BN*HSTR;

    extern __shared__ __align__(16) __half smem[];
    __half* As = smem;
    __half* Bs = smem + NSTG*SLOTA;

    int tid  = threadIdx.x;
    int lane = tid & 31;
    int wid  = tid >> 5;
    int gr   = lane >> 2;
    int ct   = lane & 3;
    int wm   = (wid >> 2) * 64;
    int wn   = (wid & 3) * (BN/4);
    int row0 = blockIdx.y * BM;
    int col0 = blockIdx.x * BN;

    uint32_t sAb = (uint32_t)__cvta_generic_to_shared(As);
    uint32_t sBb = (uint32_t)__cvta_generic_to_shared(Bs);

    // ldmatrix per-lane base addresses (within stage 0)
    uint32_t aBase = sAb + (uint32_t)((wm + ((lane>>3)&1)*8 + (lane&7))*HSTR)*2
                   + (uint32_t)(lane>>4)*16;
    uint32_t bBase = sBb + (uint32_t)((wn + (lane>>4)*8 + (lane&7))*HSTR)*2
                   + (uint32_t)((lane>>3)&1)*16;

    float acc[4][NT][4];
    #pragma unroll
    for (int i=0;i<4;i++)
        #pragma unroll
        for (int j=0;j<NT;j++)
            #pragma unroll
            for (int q=0;q<4;q++) acc[i][j][q] = 0.f;

    int nk = K / BK;

    // guarded stage load: only touches memory when kt < nk; ALWAYS commits a
    // group so wait_group accounting stays consistent.
    auto load_stage = [&](int kt){
        if (kt < nk) {
            int slot = kt % NSTG;
            int k0 = kt * BK;
            #pragma unroll
            for (int j = 0; j < 2; j++) {
                int id = tid + j*256;
                int r = id >> 2, kb = id & 3;
                cp16(sAb + (slot*SLOTA + r*HSTR)*2 + kb*16,
                     A + (size_t)(row0 + r)*K + k0 + kb*8);
            }
            #pragma unroll
            for (int j = 0; j < NLB; j++) {
                int id = tid + j*256;
                int r = id >> 2, kb = id & 3;
                cp16(sBb + (slot*SLOTB + r*HSTR)*2 + kb*16,
                     W + (size_t)(col0 + r)*K + k0 + kb*8);
            }
        }
        asm volatile("cp.async.commit_group;\n");
    };

    load_stage(0);
    load_stage(1);
    load_stage(2);

    for (int kt = 0; kt < nk; kt++) {
        asm volatile("cp.async.wait_group 2;\n");
        __syncthreads();
        load_stage(kt + 3);

        int slot = kt % NSTG;
        uint32_t aSlot = aBase + slot*SLOTA*2;
        uint32_t bSlot = bBase + slot*SLOTB*2;
        #pragma unroll
        for (int ks = 0; ks < 2; ks++) {     // two k16 steps per stage
            uint32_t ua[4][4], ub[NT][2];
            #pragma unroll
            for (int mt = 0; mt < 4; mt++)
                ldm4(ua[mt][0], ua[mt][1], ua[mt][2], ua[mt][3],
                     aSlot + mt*16*HSTR*2 + ks*32);
            #pragma unroll
            for (int p = 0; p < NP; p++)
                ldm4(ub[2*p][0], ub[2*p][1], ub[2*p+1][0], ub[2*p+1][1],
                     bSlot + p*16*HSTR*2 + ks*32);
            #pragma unroll
            for (int mt = 0; mt < 4; mt++)
                #pragma unroll
                for (int nt = 0; nt < NT; nt++)
                    mma_f16(acc[mt][nt], ua[mt], ub[nt]);
        }
    }

    #pragma unroll
    for (int mt = 0; mt < 4; mt++) {
        #pragma unroll
        for (int half = 0; half < 2; half++) {
            int r = row0 + wm + mt*16 + gr + half*8;
            size_t ro = (size_t)r * N;
            #pragma unroll
            for (int nt = 0; nt < NT; nt++) {
                int cc = col0 + wn + nt*8 + ct*2;
                float v0 = acc[mt][nt][half*2 + 0];
                float v1 = acc[mt][nt][half*2 + 1];
                if (epi == 1) {
                    v0 += bias[cc]; v1 += bias[cc+1];
                } else if (epi == 2) {
                    float t0 = v0 + bias[cc], t1 = v1 + bias[cc+1];
                    v0 = 0.5f * t0 * (1.0f + erff(t0 * 0.70710678118654752f));
                    v1 = 0.5f * t1 * (1.0f + erff(t1 * 0.70710678118654752f));
                } else if (epi == 3) {
                    v0 += bias[cc]   + rd<CT>(resid, ro+cc);
                    v1 += bias[cc+1] + rd<CT>(resid, ro+cc+1);
                } else if (epi == 7) {
                    v0 += bias[cc]   * rd<CT>(resid, ro+cc);
                    v1 += bias[cc+1] * rd<CT>(resid, ro+cc+1);
                }
                store2<CT>(C, ro + cc, v0, v1);
            }
        }
    }
}

// ==================== unified prep kernel ===================================
// One launch: fp16-converts x + 4 weight sets, builds interleaved Bcat/Ccat.
// Bcat rows are pre-scaled by gamma = exp(gl) (per state).
__global__ void prep_all(const float* __restrict__ x,    const float* __restrict__ embW,
                         const float* __restrict__ outW, const float* __restrict__ Wh,
                         const float* __restrict__ Wo,   const float* __restrict__ Bre,
                         const float* __restrict__ Bim,  const float* __restrict__ Cre,
                         const float* __restrict__ Cim,  const float* __restrict__ gl)
{
    const int N0 = M_TOT*INDIM/4;
    const int N1 = N0 + HID*INDIM/4;
    const int N2 = N1 + OUTD*HID/4;
    const int N3 = N2 + NLAYERS*MLPD*HID/4;
    const int N4 = N3 + NLAYERS*HID*MLPD/4;
    const int N5 = N4 + NLAYERS*S2*HID;
    const int N6 = N5 + NLAYERS*HID*S2;

    int i = blockIdx.x * blockDim.x + threadIdx.x;
    if (i < N4) {
        const float* src; __half* dst; int j;
        if (i < N0)      { src = x;    dst = g_xr;   j = i; }
        else if (i < N1) { src = embW; dst = g_wE;   j = i - N0; }
        else if (i < N2) { src = outW; dst = g_wOut; j = i - N1; }
        else if (i < N3) { src = Wh;   dst = g_wH;   j = i - N2; }
        else             { src = Wo;   dst = g_wO;   j = i - N3; }
        float4 v = ((const float4*)src)[j];
        ((__half2*)dst)[j*2]   = __floats2half2_rn(v.x, v.y);
        ((__half2*)dst)[j*2+1] = __floats2half2_rn(v.z, v.w);
    } else if (i < N5) {
        int j  = i - N4;
        int k  = j & (HID-1);
        int rr = (j >> 8) & (S2-1);
        int l  = j >> 17;
        int s  = rr >> 1;
        float ga = expf(gl[l*STATEN + s]);
        float v = (rr & 1) ? Bim[((size_t)l*STATEN + s)*HID + k]
                           : Bre[((size_t)l*STATEN + s)*HID + k];
        g_wB[j] = __float2half_rn(v * ga);
    } else if (i < N6) {
        int j  = i - N5;
        int kk = j & (S2-1);
        int hh = (j >> 9) & (HID-1);
        int l  = j >> 17;
        int s  = kk >> 1;
        float v = (kk & 1) ? -Cim[((size_t)l*HID + hh)*STATEN + s]
                           :  Cre[((size_t)l*HID + hh)*STATEN + s];
        g_wC[j] = __float2half_rn(v);
    }
}
#define PREP_TOTAL (M_TOT*INDIM/4 + HID*INDIM/4 + OUTD*HID/4 + NLAYERS*MLPD*HID/4 \
                    + NLAYERS*HID*MLPD/4 + NLAYERS*S2*HID + NLAYERS*HID*S2)

// ==================== fused LRU scan ========================================
__device__ __forceinline__ void lam_of(const float* nu_log, const float* th_log,
                                       int layer, int s, float& lre, float& lim)
{
    float nu = nu_log[layer*STATEN + s];
    float th = th_log[layer*STATEN + s];
    float mag = expf(-expf(nu));
    float ang = expf(th);
    float sv, cv;
    sincosf(ang, &sv, &cv);
    lre = mag * cv;
    lim = mag * sv;
}

// grid: (STATEN/SGRP, BATCHN) = (16,16), block: 1024 = 64 chunks x 16 states
// (gamma already folded into wB; bu is fp16 interleaved)
__global__ __launch_bounds__(1024)
void scan_fused(const float* __restrict__ nu_log, const float* __restrict__ th_log,
                int layer)
{
    __shared__ float se_r[NCH][SGRP], se_i[NCH][SGRP];
    __shared__ float ca_r[NCH][SGRP], ca_i[NCH][SGRP];

    int tid = threadIdx.x;
    int c   = tid >> 4;            // chunk 0..63
    int sl  = tid & (SGRP-1);      // state lane 0..15
    int s   = blockIdx.x * SGRP + sl;
    int b   = blockIdx.y;

    float lre, lim;
    lam_of(nu_log, th_log, layer, s, lre, lim);

    size_t base2 = ((size_t)b * SEQL + (size_t)c * CH) * STATEN + s;
    const __half2* bu2 = (const __half2*)g_bu;
    __half2*       st2 = (__half2*)g_st;

    // phase 1: local scan, keep chunk-end state
    {
        float sr = 0.f, si = 0.f;
        #pragma unroll 4
        for (int t = 0; t < CH; t++) {
            float2 u = __half22float2(bu2[base2 + (size_t)t * STATEN]);
            float nr = fmaf(lre, sr, fmaf(-lim, si, u.x));
            float ni = fmaf(lre, si, fmaf( lim, sr, u.y));
            sr = nr; si = ni;
        }
        se_r[c][sl] = sr; se_i[c][sl] = si;
    }
    __syncthreads();

    // phase 2: serial carry combine (first SGRP threads; for them sl == tid)
    if (tid < SGRP) {
        float ar = lre, ai = lim;     // lam^CH via LOG2CH squarings
        #pragma unroll
        for (int q = 0; q < LOG2CH; q++) {
            float nr = ar*ar - ai*ai;
            ai = 2.f * ar * ai;
            ar = nr;
        }
        float cr = 0.f, ci = 0.f;
        #pragma unroll
        for (int c2 = 0; c2 < NCH; c2++) {
            ca_r[c2][sl] = cr; ca_i[c2][sl] = ci;
            float er = se_r[c2][sl], ei = se_i[c2][sl];
            float nr = fmaf(ar, cr, fmaf(-ai, ci, er));
            float ni = fmaf(ar, ci, fmaf( ai, cr, ei));
            cr = nr; ci = ni;
        }
    }
    __syncthreads();

    // phase 3: rescan with carry-in, write fp16 states
    {
        float sr = ca_r[c][sl], si = ca_i[c][sl];
        #pragma unroll 4
        for (int t = 0; t < CH; t++) {
            float2 u = __half22float2(bu2[base2 + (size_t)t * STATEN]);
            float nr = fmaf(lre, sr, fmaf(-lim, si, u.x));
            float ni = fmaf(lre, si, fmaf( lim, sr, u.y));
            sr = nr; si = ni;
            st2[base2 + (size_t)t * STATEN] = __floats2half2_rn(sr, si);
        }
    }
}

// ==================== driver ================================================
extern "C" void kernel_launch(void* const* d_in, const int* in_sizes, int n_in,
                              void* d_out, int out_size)
{
    (void)in_sizes; (void)n_in; (void)out_size;
    const float* x    = (const float*)d_in[0];
    const float* embW = (const float*)d_in[1];
    const float* embb = (const float*)d_in[2];
    const float* nu   = (const float*)d_in[3];
    const float* th   = (const float*)d_in[4];
    const float* gl   = (const float*)d_in[5];
    const float* Bre  = (const float*)d_in[6];
    const float* Bim  = (const float*)d_in[7];
    const float* Cre  = (const float*)d_in[8];
    const float* Cim  = (const float*)d_in[9];
    const float* Dv   = (const float*)d_in[10];
    const float* Wh   = (const float*)d_in[11];
    const float* bh   = (const float*)d_in[12];
    const float* Wo   = (const float*)d_in[13];
    const float* bo   = (const float*)d_in[14];
    const float* outW = (const float*)d_in[15];
    const float* outb = (const float*)d_in[16];
    float* out = (float*)d_out;

    __half *h, *y, *z, *xr, *wE, *wB, *wC, *wH, *wO, *wOut, *stp, *bup;
    cudaGetSymbolAddress((void**)&h,    g_h);
    cudaGetSymbolAddress((void**)&y,    g_y);
    cudaGetSymbolAddress((void**)&z,    g_z);
    cudaGetSymbolAddress((void**)&xr,   g_xr);
    cudaGetSymbolAddress((void**)&wE,   g_wE);
    cudaGetSymbolAddress((void**)&wB,   g_wB);
    cudaGetSymbolAddress((void**)&wC,   g_wC);
    cudaGetSymbolAddress((void**)&wH,   g_wH);
    cudaGetSymbolAddress((void**)&wO,   g_wO);
    cudaGetSymbolAddress((void**)&wOut, g_wOut);
    cudaGetSymbolAddress((void**)&stp,  g_st);
    cudaGetSymbolAddress((void**)&bup,  g_bu);

    const int SM128 = NSTG*(BM+128)*HSTR*2;   // 81920
    cudaFuncSetAttribute((const void*)gemm_h<128,__half>, cudaFuncAttributeMaxDynamicSharedMemorySize, SM128);
    cudaFuncSetAttribute((const void*)gemm_h<128,float>,  cudaFuncAttributeMaxDynamicSharedMemorySize, SM128);

    dim3 tb(256);
    const int MB = M_TOT / BM;   // 256

    // ---- prep: ONE kernel for all conversions/concats (gamma folded) ----
    prep_all<<<(PREP_TOTAL + 255)/256, tb>>>(x, embW, outW, Wh, Wo, Bre, Bim, Cre, Cim, gl);

    // embedding: h = half(x @ embW^T + embb)
    gemm_h<128,__half><<<dim3(HID/128, MB), tb, SM128>>>(M_TOT, HID, INDIM, xr, wE, embb, (const __half*)nullptr, h, 1);

    for (int l = 0; l < NLAYERS; l++) {
        // bu = h @ Bcat^T   [M, 512] fp16 (gamma pre-applied)
        gemm_h<128,__half><<<dim3(S2/128, MB), tb, SM128>>>(M_TOT, S2, HID, h, wB + (size_t)l*S2*HID,
                                                            (const float*)nullptr, (const __half*)nullptr, bup, 0);
        // fused chunked complex scan
        scan_fused<<<dim3(STATEN/SGRP, BATCHN), 1024>>>(nu, th, l);

        // y = half([st interleaved] @ wC^T + D*h)
        gemm_h<128,__half><<<dim3(HID/128, MB), tb, SM128>>>(M_TOT, HID, S2, stp, wC + (size_t)l*HID*S2,
                                                             Dv + (size_t)l*HID, h, y, 7);
        // MLP
        gemm_h<128,__half><<<dim3(MLPD/128, MB), tb, SM128>>>(M_TOT, MLPD, HID, y, wH + (size_t)l*MLPD*HID,
                                                              bh + (size_t)l*MLPD, (const __half*)nullptr, z, 2);
        gemm_h<128,__half><<<dim3(HID/128, MB), tb, SM128>>>(M_TOT, HID, MLPD, z, wO + (size_t)l*HID*MLPD,
                                                             bo + (size_t)l*HID, y, h, 3);
    }

    // out = h @ outW^T + outb   (fp32 store)
    gemm_h<128,float><<<dim3(OUTD/128, MB), tb, SM128>>>(M_TOT, OUTD, HID, h, wOut, outb, (const float*)nullptr, out, 1);
}